// round 8
// baseline (speedup 1.0000x reference)
#include <cuda_runtime.h>
#include <cuda_bf16.h>
#include <cuda_fp16.h>
#include <cstdint>

#define S_LEN 2048
#define D_DIM 4096
#define H_Q   32
#define H_KV  8
#define HDIM  128
#define BATCH 2

// Scratch (allocation-free rule: __device__ globals)
__device__ float g_Q[BATCH * H_Q * S_LEN * HDIM];   // [B, H, S, HD]
__device__ float g_K[BATCH * H_KV * S_LEN * HDIM];  // [B, KV, S, HD]
__device__ float g_V[BATCH * H_KV * S_LEN * HDIM];  // [B, KV, S, HD]
__device__ float g_A[BATCH * S_LEN * H_Q * HDIM];   // [B, S, H, HD]

// ---------------------------------------------------------------------------
// Shared helpers
// ---------------------------------------------------------------------------
__device__ __forceinline__ void ldsm4h(uint32_t* r, const __half* p) {
    uint32_t a = (uint32_t)__cvta_generic_to_shared(p);
    asm volatile("ldmatrix.sync.aligned.m8n8.x4.shared.b16 {%0,%1,%2,%3}, [%4];"
                 : "=r"(r[0]), "=r"(r[1]), "=r"(r[2]), "=r"(r[3]) : "r"(a));
}
__device__ __forceinline__ void mma_f16(float* d, const uint32_t* a,
                                        uint32_t b0, uint32_t b1) {
    asm volatile(
        "mma.sync.aligned.m16n8k16.row.col.f32.f16.f16.f32 "
        "{%0,%1,%2,%3}, {%4,%5,%6,%7}, {%8,%9}, {%0,%1,%2,%3};"
        : "+f"(d[0]), "+f"(d[1]), "+f"(d[2]), "+f"(d[3])
        : "r"(a[0]), "r"(a[1]), "r"(a[2]), "r"(a[3]), "r"(b0), "r"(b1));
}

// ---------------------------------------------------------------------------
// FP16 NT GEMM with ldmatrix fragment loads.
// CTA 128x128, BK=32, 256 thr = 8 warps (2m x 4n), warp tile 64x32.
// Smem: row-major [row][32 halfs], stride 72 halfs (144B) -> ldmatrix
// conflict-free (row ptrs land on distinct 16B lanes).
// mode 0: row-major store.  mode 1: head-permuted store to [B, HC, S, HD].
// ---------------------------------------------------------------------------
#define AST 72

__global__ __launch_bounds__(256)
void h16gemm_nt(const float* __restrict__ A, const float* __restrict__ B,
                float* __restrict__ C, int M, int N, int K, int mode, int HC)
{
    __shared__ __half Ah[128 * AST];
    __shared__ __half Bh[128 * AST];

    const int tid = threadIdx.x;
    const int bm = blockIdx.y << 7;
    const int bn = blockIdx.x << 7;

    const int lr = tid & 127;               // row in tile
    const int lcf = (tid >> 7) << 4;        // k-col base: 0 or 16
    const float* Ag = A + (size_t)(bm + lr) * K + lcf;
    const float* Bg = B + (size_t)(bn + lr) * K + lcf;

    const int wid = tid >> 5, lane = tid & 31;
    const int wm = (wid >> 2) << 6;   // 0 or 64
    const int wn = (wid & 3) << 5;    // 0,32,64,96
    const int g = lane >> 2;
    const int c = lane & 3;

    // ldmatrix addressing (same pattern as flash QK^T)
    const int a_ro  = lane & 15;             // A row within m16 tile
    const int a_co  = (lane >> 4) << 3;      // A k-col offset (0/8)
    const int b_ro  = (lane & 7) + ((lane >> 4) << 3);   // B row within n16
    const int b_co  = ((lane >> 3) & 1) << 3;            // B k-col offset

    float acc[4][4][4];
#pragma unroll
    for (int mt = 0; mt < 4; mt++)
#pragma unroll
        for (int nt = 0; nt < 4; nt++)
#pragma unroll
            for (int e = 0; e < 4; e++) acc[mt][nt][e] = 0.f;

    float4 pa[4], pb[4];
#pragma unroll
    for (int i = 0; i < 4; i++) {
        pa[i] = *(const float4*)(Ag + (i << 2));
        pb[i] = *(const float4*)(Bg + (i << 2));
    }

    int k0 = 0;
    for (;;) {
        // Store stage: float4 -> 4 packed halfs (uint2) at [lr][lcf + 4i]
#pragma unroll
        for (int i = 0; i < 4; i++) {
            __half2 a01 = __floats2half2_rn(pa[i].x, pa[i].y);
            __half2 a23 = __floats2half2_rn(pa[i].z, pa[i].w);
            __half2 b01 = __floats2half2_rn(pb[i].x, pb[i].y);
            __half2 b23 = __floats2half2_rn(pb[i].z, pb[i].w);
            uint2 ua = make_uint2(*(uint32_t*)&a01, *(uint32_t*)&a23);
            uint2 ub = make_uint2(*(uint32_t*)&b01, *(uint32_t*)&b23);
            *(uint2*)&Ah[lr * AST + lcf + (i << 2)] = ua;
            *(uint2*)&Bh[lr * AST + lcf + (i << 2)] = ub;
        }
        __syncthreads();

        k0 += 32;
        const bool more = (k0 < K);
        if (more) {
#pragma unroll
            for (int i = 0; i < 4; i++) {
                pa[i] = *(const float4*)(Ag + k0 + (i << 2));
                pb[i] = *(const float4*)(Bg + k0 + (i << 2));
            }
        }

        // 2 k16-steps; fragments via ldmatrix.x4
#pragma unroll
        for (int ks = 0; ks < 32; ks += 16) {
            uint32_t af[4][4], bf[2][4];
#pragma unroll
            for (int mt = 0; mt < 4; mt++)
                ldsm4h(af[mt], &Ah[(wm + (mt << 4) + a_ro) * AST + ks + a_co]);
#pragma unroll
            for (int nb = 0; nb < 2; nb++)
                ldsm4h(bf[nb], &Bh[(wn + (nb << 4) + b_ro) * AST + ks + b_co]);
#pragma unroll
            for (int mt = 0; mt < 4; mt++)
#pragma unroll
                for (int nt = 0; nt < 4; nt++)
                    mma_f16(acc[mt][nt], af[mt],
                            bf[nt >> 1][(nt & 1) << 1],
                            bf[nt >> 1][((nt & 1) << 1) + 1]);
        }
        if (!more) break;
        __syncthreads();
    }

    // Epilogue: c0,c1 -> (row, 2c, 2c+1); c2,c3 -> (row+8, same cols).
    const int hcol = bn >> 7;
#pragma unroll
    for (int mt = 0; mt < 4; mt++) {
#pragma unroll
        for (int nt = 0; nt < 4; nt++) {
            const int row = bm + wm + (mt << 4) + g;
            const int col = bn + wn + (nt << 3) + (c << 1);
            float2 lo = make_float2(acc[mt][nt][0], acc[mt][nt][1]);
            float2 hi = make_float2(acc[mt][nt][2], acc[mt][nt][3]);
            if (mode == 0) {
                *(float2*)&C[(size_t)row * N + col] = lo;
                *(float2*)&C[(size_t)(row + 8) * N + col] = hi;
            } else {
                const int hd = col & (HDIM - 1);
                const int b0 = row >> 11, s0 = row & (S_LEN - 1);
                const int b1 = (row + 8) >> 11, s1 = (row + 8) & (S_LEN - 1);
                *(float2*)&C[(((size_t)(b0 * HC + hcol)) * S_LEN + s0) * HDIM + hd] = lo;
                *(float2*)&C[(((size_t)(b1 * HC + hcol)) * S_LEN + s1) * HDIM + hd] = hi;
            }
        }
    }
}

// ---------------------------------------------------------------------------
// RoPE (unchanged)
// ---------------------------------------------------------------------------
__global__ void rope_kernel(float* __restrict__ t, const float* __restrict__ cosb,
                            const float* __restrict__ sinb, int npairs)
{
    const int i = blockIdx.x * blockDim.x + threadIdx.x;
    if (i >= npairs) return;
    const int p = i & 63;
    const int s = (i >> 6) & (S_LEN - 1);
    const int bh = i >> 17;
    const float c = cosb[(s << 6) + p];
    const float sn = sinb[(s << 6) + p];
    float2* ptr = (float2*)(t + ((size_t)bh * S_LEN + s) * HDIM + (p << 1));
    const float2 v = *ptr;
    float2 o;
    o.x = v.x * c - v.y * sn;
    o.y = v.x * sn + v.y * c;
    *ptr = o;
}

// ---------------------------------------------------------------------------
// Flash attention: split-bf16 mma (proven R4 version, unchanged)
// ---------------------------------------------------------------------------
#define FSTR 136
#define FLASH_SMEM ((2 * 128 * FSTR + 4 * 64 * FSTR) * 2)

__device__ __forceinline__ void ldsm4(uint32_t* r, const __nv_bfloat16* p) {
    uint32_t a = (uint32_t)__cvta_generic_to_shared(p);
    asm volatile("ldmatrix.sync.aligned.m8n8.x4.shared.b16 {%0,%1,%2,%3}, [%4];"
                 : "=r"(r[0]), "=r"(r[1]), "=r"(r[2]), "=r"(r[3]) : "r"(a));
}
__device__ __forceinline__ void ldsm4t(uint32_t* r, const __nv_bfloat16* p) {
    uint32_t a = (uint32_t)__cvta_generic_to_shared(p);
    asm volatile("ldmatrix.sync.aligned.m8n8.x4.trans.shared.b16 {%0,%1,%2,%3}, [%4];"
                 : "=r"(r[0]), "=r"(r[1]), "=r"(r[2]), "=r"(r[3]) : "r"(a));
}
__device__ __forceinline__ void mma_bf16(float* d, const uint32_t* a,
                                         uint32_t b0, uint32_t b1) {
    asm volatile(
        "mma.sync.aligned.m16n8k16.row.col.f32.bf16.bf16.f32 "
        "{%0,%1,%2,%3}, {%4,%5,%6,%7}, {%8,%9}, {%0,%1,%2,%3};"
        : "+f"(d[0]), "+f"(d[1]), "+f"(d[2]), "+f"(d[3])
        : "r"(a[0]), "r"(a[1]), "r"(a[2]), "r"(a[3]), "r"(b0), "r"(b1));
}
__device__ __forceinline__ void bsplit(float x, __nv_bfloat16& h, __nv_bfloat16& l) {
    h = __float2bfloat16(x);
    l = __float2bfloat16(x - __bfloat162float(h));
}
__device__ __forceinline__ uint32_t packbf(float a, float b) {
    __nv_bfloat162 t = __floats2bfloat162_rn(a, b);
    return *(uint32_t*)&t;
}

__global__ __launch_bounds__(256, 1)
void flash_bf16(const float* __restrict__ Q, const float* __restrict__ K,
                const float* __restrict__ V, float* __restrict__ O)
{
    extern __shared__ __nv_bfloat16 fsm[];
    __nv_bfloat16* Qh = fsm;
    __nv_bfloat16* Ql = Qh + 128 * FSTR;
    __nv_bfloat16* Kh = Ql + 128 * FSTR;
    __nv_bfloat16* Kl = Kh + 64 * FSTR;
    __nv_bfloat16* Vh = Kl + 64 * FSTR;
    __nv_bfloat16* Vl = Vh + 64 * FSTR;

    const int tid = threadIdx.x;
    const int lane = tid & 31;
    const int w = tid >> 5;
    const int g = lane >> 2;
    const int c = lane & 3;
    const int m0 = w << 4;

    const int q0 = blockIdx.x << 7;
    const int h  = blockIdx.y;
    const int b  = blockIdx.z;
    const int kvh = h >> 2;
    const float scale = 0.08838834764831845f;

    const float* Qg = Q + (((size_t)(b * H_Q + h)) * S_LEN + q0) * HDIM;
    const float* Kg = K + ((size_t)(b * H_KV + kvh)) * S_LEN * HDIM;
    const float* Vg = V + ((size_t)(b * H_KV + kvh)) * S_LEN * HDIM;

    for (int v = tid; v < 128 * 32; v += 256) {
        const int r = v >> 5, c4 = (v & 31) << 2;
        float4 f = *(const float4*)(Qg + (size_t)r * HDIM + c4);
        f.x *= scale; f.y *= scale; f.z *= scale; f.w *= scale;
        __nv_bfloat16 h0, l0, h1, l1, h2, l2, h3, l3;
        bsplit(f.x, h0, l0); bsplit(f.y, h1, l1);
        bsplit(f.z, h2, l2); bsplit(f.w, h3, l3);
        __nv_bfloat162* qh = (__nv_bfloat162*)&Qh[r * FSTR + c4];
        __nv_bfloat162* ql = (__nv_bfloat162*)&Ql[r * FSTR + c4];
        qh[0] = __nv_bfloat162(h0, h1); qh[1] = __nv_bfloat162(h2, h3);
        ql[0] = __nv_bfloat162(l0, l1); ql[1] = __nv_bfloat162(l2, l3);
    }

    float m_run[2] = {-1e30f, -1e30f};
    float l_run[2] = {0.f, 0.f};
    float o_acc[16][4];
#pragma unroll
    for (int n = 0; n < 16; n++)
#pragma unroll
        for (int e = 0; e < 4; e++) o_acc[n][e] = 0.f;

    const int a_row = m0 + (lane & 15);
    const int a_cofs = (lane >> 4) << 3;
    const int b_rofs = (lane & 7) + ((lane >> 4) << 3);
    const int b_cofs = ((lane >> 3) & 1) << 3;
    const int v_rofs = (lane & 7) + (((lane >> 3) & 1) << 3);
    const int v_cofs = (lane >> 4) << 3;

    const int ntiles = (q0 >> 6) + 2;
    for (int t = 0; t < ntiles; t++) {
        const int j0 = t << 6;
        __syncthreads();

        for (int v = tid; v < 64 * 32; v += 256) {
            const int r = v >> 5, c4 = (v & 31) << 2;
            float4 fk = *(const float4*)(Kg + (size_t)(j0 + r) * HDIM + c4);
            float4 fv = *(const float4*)(Vg + (size_t)(j0 + r) * HDIM + c4);
            __nv_bfloat16 h0, l0, h1, l1, h2, l2, h3, l3;
            bsplit(fk.x, h0, l0); bsplit(fk.y, h1, l1);
            bsplit(fk.z, h2, l2); bsplit(fk.w, h3, l3);
            __nv_bfloat162* kh = (__nv_bfloat162*)&Kh[r * FSTR + c4];
            __nv_bfloat162* kl = (__nv_bfloat162*)&Kl[r * FSTR + c4];
            kh[0] = __nv_bfloat162(h0, h1); kh[1] = __nv_bfloat162(h2, h3);
            kl[0] = __nv_bfloat162(l0, l1); kl[1] = __nv_bfloat162(l2, l3);
            bsplit(fv.x, h0, l0); bsplit(fv.y, h1, l1);
            bsplit(fv.z, h2, l2); bsplit(fv.w, h3, l3);
            __nv_bfloat162* vh = (__nv_bfloat162*)&Vh[r * FSTR + c4];
            __nv_bfloat162* vl = (__nv_bfloat162*)&Vl[r * FSTR + c4];
            vh[0] = __nv_bfloat162(h0, h1); vh[1] = __nv_bfloat162(h2, h3);
            vl[0] = __nv_bfloat162(l0, l1); vl[1] = __nv_bfloat162(l2, l3);
        }
        __syncthreads();

        float s[8][4];
#pragma unroll
        for (int n = 0; n < 8; n++)
#pragma unroll
            for (int e = 0; e < 4; e++) s[n][e] = 0.f;

#pragma unroll
        for (int ks = 0; ks < 8; ks++) {
            uint32_t qh[4], ql[4];
            ldsm4(qh, &Qh[a_row * FSTR + (ks << 4) + a_cofs]);
            ldsm4(ql, &Ql[a_row * FSTR + (ks << 4) + a_cofs]);
#pragma unroll
            for (int jj = 0; jj < 4; jj++) {
                uint32_t kh[4], kl[4];
                const int br = (jj << 4) + b_rofs;
                const int bc = (ks << 4) + b_cofs;
                ldsm4(kh, &Kh[br * FSTR + bc]);
                ldsm4(kl, &Kl[br * FSTR + bc]);
                mma_bf16(s[2 * jj],     qh, kh[0], kh[1]);
                mma_bf16(s[2 * jj],     qh, kl[0], kl[1]);
                mma_bf16(s[2 * jj],     ql, kh[0], kh[1]);
                mma_bf16(s[2 * jj + 1], qh, kh[2], kh[3]);
                mma_bf16(s[2 * jj + 1], qh, kl[2], kl[3]);
                mma_bf16(s[2 * jj + 1], ql, kh[2], kh[3]);
            }
        }

        if (t >= ntiles - 2) {
            const int r0 = q0 + m0 + g, r1 = r0 + 8;
#pragma unroll
            for (int n = 0; n < 8; n++) {
                const int col = j0 + (n << 3) + (c << 1);
                if (col > r0)     s[n][0] = -1e30f;
                if (col + 1 > r0) s[n][1] = -1e30f;
                if (col > r1)     s[n][2] = -1e30f;
                if (col + 1 > r1) s[n][3] = -1e30f;
            }
        }

        float mx0 = -1e30f, mx1 = -1e30f;
#pragma unroll
        for (int n = 0; n < 8; n++) {
            mx0 = fmaxf(mx0, fmaxf(s[n][0], s[n][1]));
            mx1 = fmaxf(mx1, fmaxf(s[n][2], s[n][3]));
        }
        mx0 = fmaxf(mx0, __shfl_xor_sync(0xffffffffu, mx0, 1));
        mx0 = fmaxf(mx0, __shfl_xor_sync(0xffffffffu, mx0, 2));
        mx1 = fmaxf(mx1, __shfl_xor_sync(0xffffffffu, mx1, 1));
        mx1 = fmaxf(mx1, __shfl_xor_sync(0xffffffffu, mx1, 2));

        const float mn0 = fmaxf(m_run[0], mx0);
        const float mn1 = fmaxf(m_run[1], mx1);
        const float alpha0 = __expf(m_run[0] - mn0);
        const float alpha1 = __expf(m_run[1] - mn1);
        m_run[0] = mn0; m_run[1] = mn1;

        float sum0 = 0.f, sum1 = 0.f;
        uint32_t ph[16], pl[16];
#pragma unroll
        for (int n = 0; n < 8; n++) {
            float p0 = __expf(s[n][0] - mn0);
            float p1 = __expf(s[n][1] - mn0);
            float p2 = __expf(s[n][2] - mn1);
            float p3 = __expf(s[n][3] - mn1);
            sum0 += p0 + p1; sum1 += p2 + p3;
            __nv_bfloat16 h0, l0, h1, l1;
            bsplit(p0, h0, l0); bsplit(p1, h1, l1);
            ph[2 * n] = packbf(__bfloat162float(h0), __bfloat162float(h1));
            pl[2 * n] = packbf(__bfloat162float(l0), __bfloat162float(l1));
            bsplit(p2, h0, l0); bsplit(p3, h1, l1);
            ph[2 * n + 1] = packbf(__bfloat162float(h0), __bfloat162float(h1));
            pl[2 * n + 1] = packbf(__bfloat162float(l0), __bfloat162float(l1));
        }
        sum0 += __shfl_xor_sync(0xffffffffu, sum0, 1);
        sum0 += __shfl_xor_sync(0xffffffffu, sum0, 2);
        sum1 += __shfl_xor_sync(0xffffffffu, sum1, 1);
        sum1 += __shfl_xor_sync(0xffffffffu, sum1, 2);
        l_run[0] = l_run[0] * alpha0 + sum0;
        l_run[1] = l_run[1] * alpha1 + sum1;

#pragma unroll
        for (int n = 0; n < 16; n++) {
            o_acc[n][0] *= alpha0; o_acc[n][1] *= alpha0;
            o_acc[n][2] *= alpha1; o_acc[n][3] *= alpha1;
        }

#pragma unroll
        for (int kk = 0; kk < 4; kk++) {
            uint32_t pah[4] = {ph[4 * kk], ph[4 * kk + 1], ph[4 * kk + 2], ph[4 * kk + 3]};
            uint32_t pal[4] = {pl[4 * kk], pl[4 * kk + 1], pl[4 * kk + 2], pl[4 * kk + 3]};
#pragma unroll
            for (int jj = 0; jj < 8; jj++) {
                uint32_t vh[4], vl[4];
                const int vr = (kk << 4) + v_rofs;
                const int vc = (jj << 4) + v_cofs;
                ldsm4t(vh, &Vh[vr * FSTR + vc]);
                ldsm4t(vl, &Vl[vr * FSTR + vc]);
                mma_bf16(o_acc[2 * jj],     pah, vh[0], vh[1]);
                mma_bf16(o_acc[2 * jj],     pal, vh[0], vh[1]);
                mma_bf16(o_acc[2 * jj],     pah, vl[0], vl[1]);
                mma_bf16(o_acc[2 * jj + 1], pah, vh[2], vh[3]);
                mma_bf16(o_acc[2 * jj + 1], pal, vh[2], vh[3]);
                mma_bf16(o_acc[2 * jj + 1], pah, vl[2], vl[3]);
            }
        }
    }

    const float inv0 = 1.f / l_run[0];
    const float inv1 = 1.f / l_run[1];
    const int s0 = q0 + m0 + g;
    const int s1 = s0 + 8;
    float* d0 = O + (((size_t)(b * S_LEN + s0)) * H_Q + h) * HDIM;
    float* d1 = O + (((size_t)(b * S_LEN + s1)) * H_Q + h) * HDIM;
#pragma unroll
    for (int n = 0; n < 16; n++) {
        const int col = (n << 3) + (c << 1);
        *(float2*)(d0 + col) = make_float2(o_acc[n][0] * inv0, o_acc[n][1] * inv0);
        *(float2*)(d1 + col) = make_float2(o_acc[n][2] * inv1, o_acc[n][3] * inv1);
    }
}

// ---------------------------------------------------------------------------
extern "C" void kernel_launch(void* const* d_in, const int* in_sizes, int n_in,
                              void* d_out, int out_size)
{
    const float* x    = (const float*)d_in[0];
    const float* wq   = (const float*)d_in[1];
    const float* wk   = (const float*)d_in[2];
    const float* wv   = (const float*)d_in[3];
    const float* wo   = (const float*)d_in[4];
    const float* cosb = (const float*)d_in[5];
    const float* sinb = (const float*)d_in[6];
    float* out = (float*)d_out;

    float *Q, *K, *V, *A;
    cudaGetSymbolAddress((void**)&Q, g_Q);
    cudaGetSymbolAddress((void**)&K, g_K);
    cudaGetSymbolAddress((void**)&V, g_V);
    cudaGetSymbolAddress((void**)&A, g_A);

    const int M = BATCH * S_LEN;   // 4096

    // QKV projections (fp16 mma + ldmatrix, head-permuted stores)
    h16gemm_nt<<<dim3((H_Q * HDIM) / 128, M / 128), 256>>>(x, wq, Q, M, H_Q * HDIM, D_DIM, 1, H_Q);
    h16gemm_nt<<<dim3((H_KV * HDIM) / 128, M / 128), 256>>>(x, wk, K, M, H_KV * HDIM, D_DIM, 1, H_KV);
    h16gemm_nt<<<dim3((H_KV * HDIM) / 128, M / 128), 256>>>(x, wv, V, M, H_KV * HDIM, D_DIM, 1, H_KV);

    // RoPE on Q and K
    const int qpairs = BATCH * H_Q * S_LEN * (HDIM / 2);
    const int kpairs = BATCH * H_KV * S_LEN * (HDIM / 2);
    rope_kernel<<<(qpairs + 255) / 256, 256>>>(Q, cosb, sinb, qpairs);
    rope_kernel<<<(kpairs + 255) / 256, 256>>>(K, cosb, sinb, kpairs);

    // Flash attention (split-bf16 mma, proven)
    cudaFuncSetAttribute(flash_bf16, cudaFuncAttributeMaxDynamicSharedMemorySize, FLASH_SMEM);
    flash_bf16<<<dim3(S_LEN / 128, H_Q, BATCH), 256, FLASH_SMEM>>>(Q, K, V, A);

    // Output projection (fp16 mma + ldmatrix)
    h16gemm_nt<<<dim3(D_DIM / 128, M / 128), 256>>>(A, wo, out, M, D_DIM, D_DIM, 0, 0);
}

// round 9
// speedup vs baseline: 1.0276x; 1.0276x over previous
#include <cuda_runtime.h>
#include <cuda_bf16.h>
#include <cuda_fp16.h>
#include <cstdint>

#define S_LEN 2048
#define D_DIM 4096
#define H_Q   32
#define H_KV  8
#define HDIM  128
#define BATCH 2

// Scratch (allocation-free rule: __device__ globals)
__device__ float g_Q[BATCH * H_Q * S_LEN * HDIM];   // [B, H, S, HD]
__device__ float g_K[BATCH * H_KV * S_LEN * HDIM];  // [B, KV, S, HD]
__device__ float g_V[BATCH * H_KV * S_LEN * HDIM];  // [B, KV, S, HD]
__device__ float g_A[BATCH * S_LEN * H_Q * HDIM];   // [B, S, H, HD]

__device__ __forceinline__ uint32_t packh(float a, float b) {
    __half2 h = __floats2half2_rn(a, b);
    return *(uint32_t*)&h;
}

// ---------------------------------------------------------------------------
// FP16 NT GEMM core (R7-proven): CTA 128x128, BK=32, 256 thr, 8 warps.
// Smem K-pair-transposed packed fp16x2, stride 136 words (conflict-free).
// ---------------------------------------------------------------------------
#define GSTRIDE 136

struct GemmOut {
    float* C;
    int N;      // row-major width (mode 0)
    int mode;   // 0 row-major, 1 head-permuted
    int HC;     // heads for mode 1
};

__device__ __forceinline__ void h16gemm_body(
    const float* __restrict__ A, const float* __restrict__ B,
    const GemmOut& out, int bm, int bn, int K)
{
    __shared__ uint32_t As[16 * GSTRIDE];
    __shared__ uint32_t Bs[16 * GSTRIDE];

    const int tid = threadIdx.x;
    const int lr = tid & 127;
    const int lcol = (tid >> 7) << 4;
    const int lkp = lcol >> 1;
    const float* Ag = A + (size_t)(bm + lr) * K + lcol;
    const float* Bg = B + (size_t)(bn + lr) * K + lcol;

    uint32_t* Asw = &As[(size_t)lkp * GSTRIDE + lr];
    uint32_t* Bsw = &Bs[(size_t)lkp * GSTRIDE + lr];

    float4 pa[4], pb[4];
#pragma unroll
    for (int i = 0; i < 4; i++) {
        pa[i] = *(const float4*)(Ag + (i << 2));
        pb[i] = *(const float4*)(Bg + (i << 2));
    }

    const int wid = tid >> 5, lane = tid & 31;
    const int wm = (wid >> 2) << 6;
    const int wn = (wid & 3) << 5;
    const int g = lane >> 2;
    const int c = lane & 3;

    float acc[4][4][4];
#pragma unroll
    for (int mt = 0; mt < 4; mt++)
#pragma unroll
        for (int nt = 0; nt < 4; nt++)
#pragma unroll
            for (int e = 0; e < 4; e++) acc[mt][nt][e] = 0.f;

    int k0 = 0;
    for (;;) {
#pragma unroll
        for (int i = 0; i < 4; i++) {
            Asw[(i * 2 + 0) * GSTRIDE] = packh(pa[i].x, pa[i].y);
            Asw[(i * 2 + 1) * GSTRIDE] = packh(pa[i].z, pa[i].w);
            Bsw[(i * 2 + 0) * GSTRIDE] = packh(pb[i].x, pb[i].y);
            Bsw[(i * 2 + 1) * GSTRIDE] = packh(pb[i].z, pb[i].w);
        }
        __syncthreads();

        k0 += 32;
        const bool more = (k0 < K);
        if (more) {
#pragma unroll
            for (int i = 0; i < 4; i++) {
                pa[i] = *(const float4*)(Ag + k0 + (i << 2));
                pb[i] = *(const float4*)(Bg + k0 + (i << 2));
            }
        }

#pragma unroll
        for (int kq = 0; kq < 16; kq += 8) {
            uint32_t af[4][4], bf[4][2];
#pragma unroll
            for (int mt = 0; mt < 4; mt++) {
                const int m0 = wm + (mt << 4) + g;
                af[mt][0] = As[(kq + c) * GSTRIDE + m0];
                af[mt][1] = As[(kq + c) * GSTRIDE + m0 + 8];
                af[mt][2] = As[(kq + c + 4) * GSTRIDE + m0];
                af[mt][3] = As[(kq + c + 4) * GSTRIDE + m0 + 8];
            }
#pragma unroll
            for (int nt = 0; nt < 4; nt++) {
                const int n0 = wn + (nt << 3) + g;
                bf[nt][0] = Bs[(kq + c) * GSTRIDE + n0];
                bf[nt][1] = Bs[(kq + c + 4) * GSTRIDE + n0];
            }
#pragma unroll
            for (int mt = 0; mt < 4; mt++)
#pragma unroll
                for (int nt = 0; nt < 4; nt++) {
                    asm volatile(
                        "mma.sync.aligned.m16n8k16.row.col.f32.f16.f16.f32 "
                        "{%0,%1,%2,%3}, {%4,%5,%6,%7}, {%8,%9}, {%0,%1,%2,%3};"
                        : "+f"(acc[mt][nt][0]), "+f"(acc[mt][nt][1]),
                          "+f"(acc[mt][nt][2]), "+f"(acc[mt][nt][3])
                        : "r"(af[mt][0]), "r"(af[mt][1]), "r"(af[mt][2]), "r"(af[mt][3]),
                          "r"(bf[nt][0]), "r"(bf[nt][1]));
                }
        }
        if (!more) break;
        __syncthreads();
    }

    const int hcol = bn >> 7;
#pragma unroll
    for (int mt = 0; mt < 4; mt++) {
#pragma unroll
        for (int nt = 0; nt < 4; nt++) {
            const int row = bm + wm + (mt << 4) + g;
            const int col = bn + wn + (nt << 3) + (c << 1);
            float2 lo = make_float2(acc[mt][nt][0], acc[mt][nt][1]);
            float2 hi = make_float2(acc[mt][nt][2], acc[mt][nt][3]);
            if (out.mode == 0) {
                *(float2*)&out.C[(size_t)row * out.N + col] = lo;
                *(float2*)&out.C[(size_t)(row + 8) * out.N + col] = hi;
            } else {
                const int hd = col & (HDIM - 1);
                const int b0 = row >> 11, s0 = row & (S_LEN - 1);
                const int b1 = (row + 8) >> 11, s1 = (row + 8) & (S_LEN - 1);
                *(float2*)&out.C[(((size_t)(b0 * out.HC + hcol)) * S_LEN + s0) * HDIM + hd] = lo;
                *(float2*)&out.C[(((size_t)(b1 * out.HC + hcol)) * S_LEN + s1) * HDIM + hd] = hi;
            }
        }
    }
}

// Fused QKV projection: one launch, 48 n-tiles (32 Q | 8 K | 8 V) x 32 m-tiles.
__global__ __launch_bounds__(256)
void qkv_gemm(const float* __restrict__ x,
              const float* __restrict__ wq, const float* __restrict__ wk,
              const float* __restrict__ wv,
              float* __restrict__ Q, float* __restrict__ K, float* __restrict__ V)
{
    const int nt = blockIdx.x;
    const int bm = blockIdx.y << 7;
    const float* B;
    GemmOut out;
    out.mode = 1; out.N = 0;
    int bn;
    if (nt < 32)      { B = wq; out.C = Q; out.HC = H_Q;  bn = nt << 7; }
    else if (nt < 40) { B = wk; out.C = K; out.HC = H_KV; bn = (nt - 32) << 7; }
    else              { B = wv; out.C = V; out.HC = H_KV; bn = (nt - 40) << 7; }
    h16gemm_body(x, B, out, bm, bn, D_DIM);
}

// Output projection (row-major)
__global__ __launch_bounds__(256)
void o_gemm(const float* __restrict__ A, const float* __restrict__ B,
            float* __restrict__ C)
{
    GemmOut out;
    out.C = C; out.N = D_DIM; out.mode = 0; out.HC = 0;
    h16gemm_body(A, B, out, blockIdx.y << 7, blockIdx.x << 7, D_DIM);
}

// ---------------------------------------------------------------------------
// Fused RoPE over Q (first qpairs) and K (remaining kpairs)
// ---------------------------------------------------------------------------
__global__ void rope_qk_kernel(float* __restrict__ Q, float* __restrict__ K,
                               const float* __restrict__ cosb,
                               const float* __restrict__ sinb,
                               int qpairs, int total)
{
    int i = blockIdx.x * blockDim.x + threadIdx.x;
    if (i >= total) return;
    float* t = Q;
    if (i >= qpairs) { t = K; i -= qpairs; }
    const int p = i & 63;
    const int s = (i >> 6) & (S_LEN - 1);
    const int bh = i >> 17;
    const float c = cosb[(s << 6) + p];
    const float sn = sinb[(s << 6) + p];
    float2* ptr = (float2*)(t + ((size_t)bh * S_LEN + s) * HDIM + (p << 1));
    const float2 v = *ptr;
    float2 o;
    o.x = v.x * c - v.y * sn;
    o.y = v.x * sn + v.y * c;
    *ptr = o;
}

// ---------------------------------------------------------------------------
// Flash attention: split-bf16 mma (R4-proven) + longest-first + exp2 softmax
// ---------------------------------------------------------------------------
#define FSTR 136
#define FLASH_SMEM ((2 * 128 * FSTR + 4 * 64 * FSTR) * 2)

__device__ __forceinline__ void ldsm4(uint32_t* r, const __nv_bfloat16* p) {
    uint32_t a = (uint32_t)__cvta_generic_to_shared(p);
    asm volatile("ldmatrix.sync.aligned.m8n8.x4.shared.b16 {%0,%1,%2,%3}, [%4];"
                 : "=r"(r[0]), "=r"(r[1]), "=r"(r[2]), "=r"(r[3]) : "r"(a));
}
__device__ __forceinline__ void ldsm4t(uint32_t* r, const __nv_bfloat16* p) {
    uint32_t a = (uint32_t)__cvta_generic_to_shared(p);
    asm volatile("ldmatrix.sync.aligned.m8n8.x4.trans.shared.b16 {%0,%1,%2,%3}, [%4];"
                 : "=r"(r[0]), "=r"(r[1]), "=r"(r[2]), "=r"(r[3]) : "r"(a));
}
__device__ __forceinline__ void mma_bf16(float* d, const uint32_t* a,
                                         uint32_t b0, uint32_t b1) {
    asm volatile(
        "mma.sync.aligned.m16n8k16.row.col.f32.bf16.bf16.f32 "
        "{%0,%1,%2,%3}, {%4,%5,%6,%7}, {%8,%9}, {%0,%1,%2,%3};"
        : "+f"(d[0]), "+f"(d[1]), "+f"(d[2]), "+f"(d[3])
        : "r"(a[0]), "r"(a[1]), "r"(a[2]), "r"(a[3]), "r"(b0), "r"(b1));
}
__device__ __forceinline__ void bsplit(float x, __nv_bfloat16& h, __nv_bfloat16& l) {
    h = __float2bfloat16(x);
    l = __float2bfloat16(x - __bfloat162float(h));
}
__device__ __forceinline__ uint32_t packbf(float a, float b) {
    __nv_bfloat162 t = __floats2bfloat162_rn(a, b);
    return *(uint32_t*)&t;
}

__global__ __launch_bounds__(256, 1)
void flash_bf16(const float* __restrict__ Q, const float* __restrict__ K,
                const float* __restrict__ V, float* __restrict__ O)
{
    extern __shared__ __nv_bfloat16 fsm[];
    __nv_bfloat16* Qh = fsm;
    __nv_bfloat16* Ql = Qh + 128 * FSTR;
    __nv_bfloat16* Kh = Ql + 128 * FSTR;
    __nv_bfloat16* Kl = Kh + 64 * FSTR;
    __nv_bfloat16* Vh = Kl + 64 * FSTR;
    __nv_bfloat16* Vl = Vh + 64 * FSTR;

    const int tid = threadIdx.x;
    const int lane = tid & 31;
    const int w = tid >> 5;
    const int g = lane >> 2;
    const int c = lane & 3;
    const int m0 = w << 4;

    // Longest-first: blockIdx.x = 0 handles the LAST (longest causal) q-tile.
    const int q0 = (int)(gridDim.x - 1 - blockIdx.x) << 7;
    const int h  = blockIdx.y;
    const int b  = blockIdx.z;
    const int kvh = h >> 2;
    // 1/sqrt(128) * log2(e): softmax done in base-2 (exp2f = bare MUFU.EX2)
    const float scale = 0.08838834764831845f * 1.44269504088896340f;

    const float* Qg = Q + (((size_t)(b * H_Q + h)) * S_LEN + q0) * HDIM;
    const float* Kg = K + ((size_t)(b * H_KV + kvh)) * S_LEN * HDIM;
    const float* Vg = V + ((size_t)(b * H_KV + kvh)) * S_LEN * HDIM;

    for (int v = tid; v < 128 * 32; v += 256) {
        const int r = v >> 5, c4 = (v & 31) << 2;
        float4 f = *(const float4*)(Qg + (size_t)r * HDIM + c4);
        f.x *= scale; f.y *= scale; f.z *= scale; f.w *= scale;
        __nv_bfloat16 h0, l0, h1, l1, h2, l2, h3, l3;
        bsplit(f.x, h0, l0); bsplit(f.y, h1, l1);
        bsplit(f.z, h2, l2); bsplit(f.w, h3, l3);
        __nv_bfloat162* qh = (__nv_bfloat162*)&Qh[r * FSTR + c4];
        __nv_bfloat162* ql = (__nv_bfloat162*)&Ql[r * FSTR + c4];
        qh[0] = __nv_bfloat162(h0, h1); qh[1] = __nv_bfloat162(h2, h3);
        ql[0] = __nv_bfloat162(l0, l1); ql[1] = __nv_bfloat162(l2, l3);
    }

    float m_run[2] = {-1e30f, -1e30f};
    float l_run[2] = {0.f, 0.f};
    float o_acc[16][4];
#pragma unroll
    for (int n = 0; n < 16; n++)
#pragma unroll
        for (int e = 0; e < 4; e++) o_acc[n][e] = 0.f;

    const int a_row = m0 + (lane & 15);
    const int a_cofs = (lane >> 4) << 3;
    const int b_rofs = (lane & 7) + ((lane >> 4) << 3);
    const int b_cofs = ((lane >> 3) & 1) << 3;
    const int v_rofs = (lane & 7) + (((lane >> 3) & 1) << 3);
    const int v_cofs = (lane >> 4) << 3;

    const int ntiles = (q0 >> 6) + 2;
    for (int t = 0; t < ntiles; t++) {
        const int j0 = t << 6;
        __syncthreads();

        for (int v = tid; v < 64 * 32; v += 256) {
            const int r = v >> 5, c4 = (v & 31) << 2;
            float4 fk = *(const float4*)(Kg + (size_t)(j0 + r) * HDIM + c4);
            float4 fv = *(const float4*)(Vg + (size_t)(j0 + r) * HDIM + c4);
            __nv_bfloat16 h0, l0, h1, l1, h2, l2, h3, l3;
            bsplit(fk.x, h0, l0); bsplit(fk.y, h1, l1);
            bsplit(fk.z, h2, l2); bsplit(fk.w, h3, l3);
            __nv_bfloat162* kh = (__nv_bfloat162*)&Kh[r * FSTR + c4];
            __nv_bfloat162* kl = (__nv_bfloat162*)&Kl[r * FSTR + c4];
            kh[0] = __nv_bfloat162(h0, h1); kh[1] = __nv_bfloat162(h2, h3);
            kl[0] = __nv_bfloat162(l0, l1); kl[1] = __nv_bfloat162(l2, l3);
            bsplit(fv.x, h0, l0); bsplit(fv.y, h1, l1);
            bsplit(fv.z, h2, l2); bsplit(fv.w, h3, l3);
            __nv_bfloat162* vh = (__nv_bfloat162*)&Vh[r * FSTR + c4];
            __nv_bfloat162* vl = (__nv_bfloat162*)&Vl[r * FSTR + c4];
            vh[0] = __nv_bfloat162(h0, h1); vh[1] = __nv_bfloat162(h2, h3);
            vl[0] = __nv_bfloat162(l0, l1); vl[1] = __nv_bfloat162(l2, l3);
        }
        __syncthreads();

        float s[8][4];
#pragma unroll
        for (int n = 0; n < 8; n++)
#pragma unroll
            for (int e = 0; e < 4; e++) s[n][e] = 0.f;

#pragma unroll
        for (int ks = 0; ks < 8; ks++) {
            uint32_t qh[4], ql[4];
            ldsm4(qh, &Qh[a_row * FSTR + (ks << 4) + a_cofs]);
            ldsm4(ql, &Ql[a_row * FSTR + (ks << 4) + a_cofs]);
#pragma unroll
            for (int jj = 0; jj < 4; jj++) {
                uint32_t kh[4], kl[4];
                const int br = (jj << 4) + b_rofs;
                const int bc = (ks << 4) + b_cofs;
                ldsm4(kh, &Kh[br * FSTR + bc]);
                ldsm4(kl, &Kl[br * FSTR + bc]);
                mma_bf16(s[2 * jj],     qh, kh[0], kh[1]);
                mma_bf16(s[2 * jj],     qh, kl[0], kl[1]);
                mma_bf16(s[2 * jj],     ql, kh[0], kh[1]);
                mma_bf16(s[2 * jj + 1], qh, kh[2], kh[3]);
                mma_bf16(s[2 * jj + 1], qh, kl[2], kl[3]);
                mma_bf16(s[2 * jj + 1], ql, kh[2], kh[3]);
            }
        }

        if (t >= ntiles - 2) {
            const int r0 = q0 + m0 + g, r1 = r0 + 8;
#pragma unroll
            for (int n = 0; n < 8; n++) {
                const int col = j0 + (n << 3) + (c << 1);
                if (col > r0)     s[n][0] = -1e30f;
                if (col + 1 > r0) s[n][1] = -1e30f;
                if (col > r1)     s[n][2] = -1e30f;
                if (col + 1 > r1) s[n][3] = -1e30f;
            }
        }

        float mx0 = -1e30f, mx1 = -1e30f;
#pragma unroll
        for (int n = 0; n < 8; n++) {
            mx0 = fmaxf(mx0, fmaxf(s[n][0], s[n][1]));
            mx1 = fmaxf(mx1, fmaxf(s[n][2], s[n][3]));
        }
        mx0 = fmaxf(mx0, __shfl_xor_sync(0xffffffffu, mx0, 1));
        mx0 = fmaxf(mx0, __shfl_xor_sync(0xffffffffu, mx0, 2));
        mx1 = fmaxf(mx1, __shfl_xor_sync(0xffffffffu, mx1, 1));
        mx1 = fmaxf(mx1, __shfl_xor_sync(0xffffffffu, mx1, 2));

        const float mn0 = fmaxf(m_run[0], mx0);
        const float mn1 = fmaxf(m_run[1], mx1);
        const float alpha0 = exp2f(m_run[0] - mn0);
        const float alpha1 = exp2f(m_run[1] - mn1);
        m_run[0] = mn0; m_run[1] = mn1;

        float sum0 = 0.f, sum1 = 0.f;
        uint32_t ph[16], pl[16];
#pragma unroll
        for (int n = 0; n < 8; n++) {
            float p0 = exp2f(s[n][0] - mn0);
            float p1 = exp2f(s[n][1] - mn0);
            float p2 = exp2f(s[n][2] - mn1);
            float p3 = exp2f(s[n][3] - mn1);
            sum0 += p0 + p1; sum1 += p2 + p3;
            __nv_bfloat16 h0, l0, h1, l1;
            bsplit(p0, h0, l0); bsplit(p1, h1, l1);
            ph[2 * n] = packbf(__bfloat162float(h0), __bfloat162float(h1));
            pl[2 * n] = packbf(__bfloat162float(l0), __bfloat162float(l1));
            bsplit(p2, h0, l0); bsplit(p3, h1, l1);
            ph[2 * n + 1] = packbf(__bfloat162float(h0), __bfloat162float(h1));
            pl[2 * n + 1] = packbf(__bfloat162float(l0), __bfloat162float(l1));
        }
        sum0 += __shfl_xor_sync(0xffffffffu, sum0, 1);
        sum0 += __shfl_xor_sync(0xffffffffu, sum0, 2);
        sum1 += __shfl_xor_sync(0xffffffffu, sum1, 1);
        sum1 += __shfl_xor_sync(0xffffffffu, sum1, 2);
        l_run[0] = l_run[0] * alpha0 + sum0;
        l_run[1] = l_run[1] * alpha1 + sum1;

#pragma unroll
        for (int n = 0; n < 16; n++) {
            o_acc[n][0] *= alpha0; o_acc[n][1] *= alpha0;
            o_acc[n][2] *= alpha1; o_acc[n][3] *= alpha1;
        }

#pragma unroll
        for (int kk = 0; kk < 4; kk++) {
            uint32_t pah[4] = {ph[4 * kk], ph[4 * kk + 1], ph[4 * kk + 2], ph[4 * kk + 3]};
            uint32_t pal[4] = {pl[4 * kk], pl[4 * kk + 1], pl[4 * kk + 2], pl[4 * kk + 3]};
#pragma unroll
            for (int jj = 0; jj < 8; jj++) {
                uint32_t vh[4], vl[4];
                const int vr = (kk << 4) + v_rofs;
                const int vc = (jj << 4) + v_cofs;
                ldsm4t(vh, &Vh[vr * FSTR + vc]);
                ldsm4t(vl, &Vl[vr * FSTR + vc]);
                mma_bf16(o_acc[2 * jj],     pah, vh[0], vh[1]);
                mma_bf16(o_acc[2 * jj],     pal, vh[0], vh[1]);
                mma_bf16(o_acc[2 * jj],     pah, vl[0], vl[1]);
                mma_bf16(o_acc[2 * jj + 1], pah, vh[2], vh[3]);
                mma_bf16(o_acc[2 * jj + 1], pal, vh[2], vh[3]);
                mma_bf16(o_acc[2 * jj + 1], pah, vl[2], vl[3]);
            }
        }
    }

    const float inv0 = 1.f / l_run[0];
    const float inv1 = 1.f / l_run[1];
    const int s0 = q0 + m0 + g;
    const int s1 = s0 + 8;
    float* d0 = O + (((size_t)(b * S_LEN + s0)) * H_Q + h) * HDIM;
    float* d1 = O + (((size_t)(b * S_LEN + s1)) * H_Q + h) * HDIM;
#pragma unroll
    for (int n = 0; n < 16; n++) {
        const int col = (n << 3) + (c << 1);
        *(float2*)(d0 + col) = make_float2(o_acc[n][0] * inv0, o_acc[n][1] * inv0);
        *(float2*)(d1 + col) = make_float2(o_acc[n][2] * inv1, o_acc[n][3] * inv1);
    }
}

// ---------------------------------------------------------------------------
extern "C" void kernel_launch(void* const* d_in, const int* in_sizes, int n_in,
                              void* d_out, int out_size)
{
    const float* x    = (const float*)d_in[0];
    const float* wq   = (const float*)d_in[1];
    const float* wk   = (const float*)d_in[2];
    const float* wv   = (const float*)d_in[3];
    const float* wo   = (const float*)d_in[4];
    const float* cosb = (const float*)d_in[5];
    const float* sinb = (const float*)d_in[6];
    float* out = (float*)d_out;

    float *Q, *K, *V, *A;
    cudaGetSymbolAddress((void**)&Q, g_Q);
    cudaGetSymbolAddress((void**)&K, g_K);
    cudaGetSymbolAddress((void**)&V, g_V);
    cudaGetSymbolAddress((void**)&A, g_A);

    const int M = BATCH * S_LEN;   // 4096

    // Fused QKV projection: one launch, 48 x 32 CTAs
    qkv_gemm<<<dim3(48, M / 128), 256>>>(x, wq, wk, wv, Q, K, V);

    // Fused RoPE on Q and K
    const int qpairs = BATCH * H_Q * S_LEN * (HDIM / 2);
    const int kpairs = BATCH * H_KV * S_LEN * (HDIM / 2);
    rope_qk_kernel<<<(qpairs + kpairs + 255) / 256, 256>>>(
        Q, K, cosb, sinb, qpairs, qpairs + kpairs);

    // Flash attention (split-bf16 mma, longest-first, exp2 softmax)
    cudaFuncSetAttribute(flash_bf16, cudaFuncAttributeMaxDynamicSharedMemorySize, FLASH_SMEM);
    flash_bf16<<<dim3(S_LEN / 128, H_Q, BATCH), 256, FLASH_SMEM>>>(Q, K, V, A);

    // Output projection
    o_gemm<<<dim3(D_DIM / 128, M / 128), 256>>>(A, wo, out);
}

// round 10
// speedup vs baseline: 2.2756x; 2.2145x over previous
#include <cuda_runtime.h>
#include <cuda_bf16.h>
#include <cuda_fp16.h>
#include <cstdint>

#define S_LEN 2048
#define D_DIM 4096
#define H_Q   32
#define H_KV  8
#define HDIM  128
#define BATCH 2
#define K_DIM 4096

// Scratch (allocation-free rule: __device__ globals)
__device__ float g_Q[BATCH * H_Q * S_LEN * HDIM];    // [B, H, S, HD] fp32
__device__ float g_K[BATCH * H_KV * S_LEN * HDIM];
__device__ float g_V[BATCH * H_KV * S_LEN * HDIM];
__device__ __half g_x16[4096 * 4096];                // x   fp16
__device__ __half g_wq16[4096 * 4096];
__device__ __half g_wk16[1024 * 4096];
__device__ __half g_wv16[1024 * 4096];
__device__ __half g_wo16[4096 * 4096];
__device__ __half g_Ah[4096 * 4096];                 // flash out, fp16

// ---------------------------------------------------------------------------
// fp32 -> fp16 convert (vectorized)
// ---------------------------------------------------------------------------
__global__ void f2h(const float* __restrict__ s, __half* __restrict__ d, int n4)
{
    const int i = blockIdx.x * blockDim.x + threadIdx.x;
    if (i >= n4) return;
    const float4 f = ((const float4*)s)[i];
    __half2 h0 = __floats2half2_rn(f.x, f.y);
    __half2 h1 = __floats2half2_rn(f.z, f.w);
    ((uint2*)d)[i] = make_uint2(*(uint32_t*)&h0, *(uint32_t*)&h1);
}

// ---------------------------------------------------------------------------
// FP16 NT GEMM, all-fp16 global operands, cp.async 3-stage pipeline.
// CTA 128m x 256n, BK=64, 256 thr = 8 warps (2m x 4n), warp tile 64x64.
// Smem: row-major [row][64 halfs], stride 144 B (36 words) -> fragment LDS
// bank = (4g + c) conflict-free. A rows 0..127, B rows 128..383 per stage.
// mode 0: row-major store.  mode 1: head-permuted store to [B, HC, S, HD].
// ---------------------------------------------------------------------------
#define STG_BYTES (384 * 144)            // 55296
#define NSTG 3
#define GEMM_SMEM (NSTG * STG_BYTES)     // 165888

__device__ __forceinline__ void cp16(uint32_t dst, const void* src) {
    asm volatile("cp.async.ca.shared.global [%0], [%1], 16;"
                 :: "r"(dst), "l"(src));
}
__device__ __forceinline__ void mma_h(float* d, const uint32_t* a,
                                      uint32_t b0, uint32_t b1) {
    asm volatile(
        "mma.sync.aligned.m16n8k16.row.col.f32.f16.f16.f32 "
        "{%0,%1,%2,%3}, {%4,%5,%6,%7}, {%8,%9}, {%0,%1,%2,%3};"
        : "+f"(d[0]), "+f"(d[1]), "+f"(d[2]), "+f"(d[3])
        : "r"(a[0]), "r"(a[1]), "r"(a[2]), "r"(a[3]), "r"(b0), "r"(b1));
}

__device__ __forceinline__ void hgemm_issue(
    uint32_t sdst, const __half* __restrict__ A, const __half* __restrict__ B,
    int bm, int bn, int k0, int tid)
{
    // 3072 chunks of 16B: q = tid + 256*i; row = q>>3 (0..383), j = q&7.
    // rows 0..127 -> A, 128..383 -> B. Per-8-lane group: row fixed, j 0..7
    // -> global 128B contiguous (perfect), smem 16B-cols distinct (row+j mod 8).
#pragma unroll
    for (int i = 0; i < 4; i++) {
        const int q = tid + (i << 8);
        const int row = q >> 3, j = q & 7;
        cp16(sdst + row * 144 + (j << 4),
             A + (size_t)(bm + row) * K_DIM + k0 + (j << 3));
    }
#pragma unroll
    for (int i = 4; i < 12; i++) {
        const int q = tid + (i << 8);
        const int row = q >> 3, j = q & 7;
        cp16(sdst + row * 144 + (j << 4),
             B + (size_t)(bn + row - 128) * K_DIM + k0 + (j << 3));
    }
}

__global__ __launch_bounds__(256, 1)
void hgemm(const __half* __restrict__ A, const __half* __restrict__ B,
           float* __restrict__ C, int N, int mode, int HC)
{
    extern __shared__ char gsm[];
    const uint32_t sbase = (uint32_t)__cvta_generic_to_shared(gsm);
    const int tid = threadIdx.x;
    const int bm = blockIdx.y << 7;
    const int bn = blockIdx.x << 8;

    const int wid = tid >> 5, lane = tid & 31;
    const int wm = (wid >> 2) << 6;   // 0 or 64
    const int wn = (wid & 3) << 6;    // 0,64,128,192
    const int g = lane >> 2;
    const int c = lane & 3;

    float acc[4][8][4];
#pragma unroll
    for (int mt = 0; mt < 4; mt++)
#pragma unroll
        for (int nt = 0; nt < 8; nt++)
#pragma unroll
            for (int e = 0; e < 4; e++) acc[mt][nt][e] = 0.f;

    // Prologue: stages 0,1 in flight
    hgemm_issue(sbase, A, B, bm, bn, 0, tid);
    asm volatile("cp.async.commit_group;" ::: "memory");
    hgemm_issue(sbase + STG_BYTES, A, B, bm, bn, 64, tid);
    asm volatile("cp.async.commit_group;" ::: "memory");

    const int NST = K_DIM / 64;   // 64 stages
    int buf = 0;
    for (int s = 0; s < NST; s++) {
        asm volatile("cp.async.wait_group 1;" ::: "memory");
        __syncthreads();

        const uint32_t* Sw = (const uint32_t*)(gsm + buf * STG_BYTES);
        const uint32_t* Bw = Sw + 128 * 36;
#pragma unroll
        for (int kq = 0; kq < 4; kq++) {
            const int kc = (kq << 3) + c;
            uint32_t af[4][4];
#pragma unroll
            for (int mt = 0; mt < 4; mt++) {
                const int m0 = wm + (mt << 4) + g;
                af[mt][0] = Sw[m0 * 36 + kc];
                af[mt][1] = Sw[(m0 + 8) * 36 + kc];
                af[mt][2] = Sw[m0 * 36 + kc + 4];
                af[mt][3] = Sw[(m0 + 8) * 36 + kc + 4];
            }
#pragma unroll
            for (int nt = 0; nt < 8; nt++) {
                const int n0 = wn + (nt << 3) + g;
                const uint32_t b0 = Bw[n0 * 36 + kc];
                const uint32_t b1 = Bw[n0 * 36 + kc + 4];
#pragma unroll
                for (int mt = 0; mt < 4; mt++)
                    mma_h(acc[mt][nt], af[mt], b0, b1);
            }
        }
        __syncthreads();   // all warps done reading buf before overwrite

        if (s + 2 < NST) {
            const int nb = (buf + 2 >= NSTG) ? buf + 2 - NSTG : buf + 2;
            hgemm_issue(sbase + nb * STG_BYTES, A, B, bm, bn, (s + 2) << 6, tid);
            asm volatile("cp.async.commit_group;" ::: "memory");
        }
        buf = (buf + 1 == NSTG) ? 0 : buf + 1;
    }

    // Epilogue (direct global stores, same fragment->element map as R7)
#pragma unroll
    for (int mt = 0; mt < 4; mt++) {
#pragma unroll
        for (int nt = 0; nt < 8; nt++) {
            const int row = bm + wm + (mt << 4) + g;
            const int col = bn + wn + (nt << 3) + (c << 1);
            float2 lo = make_float2(acc[mt][nt][0], acc[mt][nt][1]);
            float2 hi = make_float2(acc[mt][nt][2], acc[mt][nt][3]);
            if (mode == 0) {
                *(float2*)&C[(size_t)row * N + col] = lo;
                *(float2*)&C[(size_t)(row + 8) * N + col] = hi;
            } else {
                const int hh = col >> 7, hd = col & (HDIM - 1);
                const int b0 = row >> 11, s0 = row & (S_LEN - 1);
                const int b1 = (row + 8) >> 11, s1 = (row + 8) & (S_LEN - 1);
                *(float2*)&C[(((size_t)(b0 * HC + hh)) * S_LEN + s0) * HDIM + hd] = lo;
                *(float2*)&C[(((size_t)(b1 * HC + hh)) * S_LEN + s1) * HDIM + hd] = hi;
            }
        }
    }
}

// ---------------------------------------------------------------------------
// RoPE (R7 version)
// ---------------------------------------------------------------------------
__global__ void rope_kernel(float* __restrict__ t, const float* __restrict__ cosb,
                            const float* __restrict__ sinb, int npairs)
{
    const int i = blockIdx.x * blockDim.x + threadIdx.x;
    if (i >= npairs) return;
    const int p = i & 63;
    const int s = (i >> 6) & (S_LEN - 1);
    const int bh = i >> 17;
    const float c = cosb[(s << 6) + p];
    const float sn = sinb[(s << 6) + p];
    float2* ptr = (float2*)(t + ((size_t)bh * S_LEN + s) * HDIM + (p << 1));
    const float2 v = *ptr;
    float2 o;
    o.x = v.x * c - v.y * sn;
    o.y = v.x * sn + v.y * c;
    *ptr = o;
}

// ---------------------------------------------------------------------------
// Flash attention: split-bf16 mma (exact R7/R4), but writes A as fp16
// ---------------------------------------------------------------------------
#define FSTR 136
#define FLASH_SMEM ((2 * 128 * FSTR + 4 * 64 * FSTR) * 2)

__device__ __forceinline__ void ldsm4(uint32_t* r, const __nv_bfloat16* p) {
    uint32_t a = (uint32_t)__cvta_generic_to_shared(p);
    asm volatile("ldmatrix.sync.aligned.m8n8.x4.shared.b16 {%0,%1,%2,%3}, [%4];"
                 : "=r"(r[0]), "=r"(r[1]), "=r"(r[2]), "=r"(r[3]) : "r"(a));
}
__device__ __forceinline__ void ldsm4t(uint32_t* r, const __nv_bfloat16* p) {
    uint32_t a = (uint32_t)__cvta_generic_to_shared(p);
    asm volatile("ldmatrix.sync.aligned.m8n8.x4.trans.shared.b16 {%0,%1,%2,%3}, [%4];"
                 : "=r"(r[0]), "=r"(r[1]), "=r"(r[2]), "=r"(r[3]) : "r"(a));
}
__device__ __forceinline__ void mma_bf16(float* d, const uint32_t* a,
                                         uint32_t b0, uint32_t b1) {
    asm volatile(
        "mma.sync.aligned.m16n8k16.row.col.f32.bf16.bf16.f32 "
        "{%0,%1,%2,%3}, {%4,%5,%6,%7}, {%8,%9}, {%0,%1,%2,%3};"
        : "+f"(d[0]), "+f"(d[1]), "+f"(d[2]), "+f"(d[3])
        : "r"(a[0]), "r"(a[1]), "r"(a[2]), "r"(a[3]), "r"(b0), "r"(b1));
}
__device__ __forceinline__ void bsplit(float x, __nv_bfloat16& h, __nv_bfloat16& l) {
    h = __float2bfloat16(x);
    l = __float2bfloat16(x - __bfloat162float(h));
}
__device__ __forceinline__ uint32_t packbf(float a, float b) {
    __nv_bfloat162 t = __floats2bfloat162_rn(a, b);
    return *(uint32_t*)&t;
}

__global__ __launch_bounds__(256, 1)
void flash_bf16(const float* __restrict__ Q, const float* __restrict__ K,
                const float* __restrict__ V, __half* __restrict__ O)
{
    extern __shared__ __nv_bfloat16 fsm[];
    __nv_bfloat16* Qh = fsm;
    __nv_bfloat16* Ql = Qh + 128 * FSTR;
    __nv_bfloat16* Kh = Ql + 128 * FSTR;
    __nv_bfloat16* Kl = Kh + 64 * FSTR;
    __nv_bfloat16* Vh = Kl + 64 * FSTR;
    __nv_bfloat16* Vl = Vh + 64 * FSTR;

    const int tid = threadIdx.x;
    const int lane = tid & 31;
    const int w = tid >> 5;
    const int g = lane >> 2;
    const int c = lane & 3;
    const int m0 = w << 4;

    const int q0 = blockIdx.x << 7;
    const int h  = blockIdx.y;
    const int b  = blockIdx.z;
    const int kvh = h >> 2;
    const float scale = 0.08838834764831845f;

    const float* Qg = Q + (((size_t)(b * H_Q + h)) * S_LEN + q0) * HDIM;
    const float* Kg = K + ((size_t)(b * H_KV + kvh)) * S_LEN * HDIM;
    const float* Vg = V + ((size_t)(b * H_KV + kvh)) * S_LEN * HDIM;

    for (int v = tid; v < 128 * 32; v += 256) {
        const int r = v >> 5, c4 = (v & 31) << 2;
        float4 f = *(const float4*)(Qg + (size_t)r * HDIM + c4);
        f.x *= scale; f.y *= scale; f.z *= scale; f.w *= scale;
        __nv_bfloat16 h0, l0, h1, l1, h2, l2, h3, l3;
        bsplit(f.x, h0, l0); bsplit(f.y, h1, l1);
        bsplit(f.z, h2, l2); bsplit(f.w, h3, l3);
        __nv_bfloat162* qh = (__nv_bfloat162*)&Qh[r * FSTR + c4];
        __nv_bfloat162* ql = (__nv_bfloat162*)&Ql[r * FSTR + c4];
        qh[0] = __nv_bfloat162(h0, h1); qh[1] = __nv_bfloat162(h2, h3);
        ql[0] = __nv_bfloat162(l0, l1); ql[1] = __nv_bfloat162(l2, l3);
    }

    float m_run[2] = {-1e30f, -1e30f};
    float l_run[2] = {0.f, 0.f};
    float o_acc[16][4];
#pragma unroll
    for (int n = 0; n < 16; n++)
#pragma unroll
        for (int e = 0; e < 4; e++) o_acc[n][e] = 0.f;

    const int a_row = m0 + (lane & 15);
    const int a_cofs = (lane >> 4) << 3;
    const int b_rofs = (lane & 7) + ((lane >> 4) << 3);
    const int b_cofs = ((lane >> 3) & 1) << 3;
    const int v_rofs = (lane & 7) + (((lane >> 3) & 1) << 3);
    const int v_cofs = (lane >> 4) << 3;

    const int ntiles = (q0 >> 6) + 2;
    for (int t = 0; t < ntiles; t++) {
        const int j0 = t << 6;
        __syncthreads();

        for (int v = tid; v < 64 * 32; v += 256) {
            const int r = v >> 5, c4 = (v & 31) << 2;
            float4 fk = *(const float4*)(Kg + (size_t)(j0 + r) * HDIM + c4);
            float4 fv = *(const float4*)(Vg + (size_t)(j0 + r) * HDIM + c4);
            __nv_bfloat16 h0, l0, h1, l1, h2, l2, h3, l3;
            bsplit(fk.x, h0, l0); bsplit(fk.y, h1, l1);
            bsplit(fk.z, h2, l2); bsplit(fk.w, h3, l3);
            __nv_bfloat162* kh = (__nv_bfloat162*)&Kh[r * FSTR + c4];
            __nv_bfloat162* kl = (__nv_bfloat162*)&Kl[r * FSTR + c4];
            kh[0] = __nv_bfloat162(h0, h1); kh[1] = __nv_bfloat162(h2, h3);
            kl[0] = __nv_bfloat162(l0, l1); kl[1] = __nv_bfloat162(l2, l3);
            bsplit(fv.x, h0, l0); bsplit(fv.y, h1, l1);
            bsplit(fv.z, h2, l2); bsplit(fv.w, h3, l3);
            __nv_bfloat162* vh = (__nv_bfloat162*)&Vh[r * FSTR + c4];
            __nv_bfloat162* vl = (__nv_bfloat162*)&Vl[r * FSTR + c4];
            vh[0] = __nv_bfloat162(h0, h1); vh[1] = __nv_bfloat162(h2, h3);
            vl[0] = __nv_bfloat162(l0, l1); vl[1] = __nv_bfloat162(l2, l3);
        }
        __syncthreads();

        float s[8][4];
#pragma unroll
        for (int n = 0; n < 8; n++)
#pragma unroll
            for (int e = 0; e < 4; e++) s[n][e] = 0.f;

#pragma unroll
        for (int ks = 0; ks < 8; ks++) {
            uint32_t qh[4], ql[4];
            ldsm4(qh, &Qh[a_row * FSTR + (ks << 4) + a_cofs]);
            ldsm4(ql, &Ql[a_row * FSTR + (ks << 4) + a_cofs]);
#pragma unroll
            for (int jj = 0; jj < 4; jj++) {
                uint32_t kh[4], kl[4];
                const int br = (jj << 4) + b_rofs;
                const int bc = (ks << 4) + b_cofs;
                ldsm4(kh, &Kh[br * FSTR + bc]);
                ldsm4(kl, &Kl[br * FSTR + bc]);
                mma_bf16(s[2 * jj],     qh, kh[0], kh[1]);
                mma_bf16(s[2 * jj],     qh, kl[0], kl[1]);
                mma_bf16(s[2 * jj],     ql, kh[0], kh[1]);
                mma_bf16(s[2 * jj + 1], qh, kh[2], kh[3]);
                mma_bf16(s[2 * jj + 1], qh, kl[2], kl[3]);
                mma_bf16(s[2 * jj + 1], ql, kh[2], kh[3]);
            }
        }

        if (t >= ntiles - 2) {
            const int r0 = q0 + m0 + g, r1 = r0 + 8;
#pragma unroll
            for (int n = 0; n < 8; n++) {
                const int col = j0 + (n << 3) + (c << 1);
                if (col > r0)     s[n][0] = -1e30f;
                if (col + 1 > r0) s[n][1] = -1e30f;
                if (col > r1)     s[n][2] = -1e30f;
                if (col + 1 > r1) s[n][3] = -1e30f;
            }
        }

        float mx0 = -1e30f, mx1 = -1e30f;
#pragma unroll
        for (int n = 0; n < 8; n++) {
            mx0 = fmaxf(mx0, fmaxf(s[n][0], s[n][1]));
            mx1 = fmaxf(mx1, fmaxf(s[n][2], s[n][3]));
        }
        mx0 = fmaxf(mx0, __shfl_xor_sync(0xffffffffu, mx0, 1));
        mx0 = fmaxf(mx0, __shfl_xor_sync(0xffffffffu, mx0, 2));
        mx1 = fmaxf(mx1, __shfl_xor_sync(0xffffffffu, mx1, 1));
        mx1 = fmaxf(mx1, __shfl_xor_sync(0xffffffffu, mx1, 2));

        const float mn0 = fmaxf(m_run[0], mx0);
        const float mn1 = fmaxf(m_run[1], mx1);
        const float alpha0 = __expf(m_run[0] - mn0);
        const float alpha1 = __expf(m_run[1] - mn1);
        m_run[0] = mn0; m_run[1] = mn1;

        float sum0 = 0.f, sum1 = 0.f;
        uint32_t ph[16], pl[16];
#pragma unroll
        for (int n = 0; n < 8; n++) {
            float p0 = __expf(s[n][0] - mn0);
            float p1 = __expf(s[n][1] - mn0);
            float p2 = __expf(s[n][2] - mn1);
            float p3 = __expf(s[n][3] - mn1);
            sum0 += p0 + p1; sum1 += p2 + p3;
            __nv_bfloat16 h0, l0, h1, l1;
            bsplit(p0, h0, l0); bsplit(p1, h1, l1);
            ph[2 * n] = packbf(__bfloat162float(h0), __bfloat162float(h1));
            pl[2 * n] = packbf(__bfloat162float(l0), __bfloat162float(l1));
            bsplit(p2, h0, l0); bsplit(p3, h1, l1);
            ph[2 * n + 1] = packbf(__bfloat162float(h0), __bfloat162float(h1));
            pl[2 * n + 1] = packbf(__bfloat162float(l0), __bfloat162float(l1));
        }
        sum0 += __shfl_xor_sync(0xffffffffu, sum0, 1);
        sum0 += __shfl_xor_sync(0xffffffffu, sum0, 2);
        sum1 += __shfl_xor_sync(0xffffffffu, sum1, 1);
        sum1 += __shfl_xor_sync(0xffffffffu, sum1, 2);
        l_run[0] = l_run[0] * alpha0 + sum0;
        l_run[1] = l_run[1] * alpha1 + sum1;

#pragma unroll
        for (int n = 0; n < 16; n++) {
            o_acc[n][0] *= alpha0; o_acc[n][1] *= alpha0;
            o_acc[n][2] *= alpha1; o_acc[n][3] *= alpha1;
        }

#pragma unroll
        for (int kk = 0; kk < 4; kk++) {
            uint32_t pah[4] = {ph[4 * kk], ph[4 * kk + 1], ph[4 * kk + 2], ph[4 * kk + 3]};
            uint32_t pal[4] = {pl[4 * kk], pl[4 * kk + 1], pl[4 * kk + 2], pl[4 * kk + 3]};
#pragma unroll
            for (int jj = 0; jj < 8; jj++) {
                uint32_t vh[4], vl[4];
                const int vr = (kk << 4) + v_rofs;
                const int vc = (jj << 4) + v_cofs;
                ldsm4t(vh, &Vh[vr * FSTR + vc]);
                ldsm4t(vl, &Vl[vr * FSTR + vc]);
                mma_bf16(o_acc[2 * jj],     pah, vh[0], vh[1]);
                mma_bf16(o_acc[2 * jj],     pal, vh[0], vh[1]);
                mma_bf16(o_acc[2 * jj],     pah, vl[0], vl[1]);
                mma_bf16(o_acc[2 * jj + 1], pah, vh[2], vh[3]);
                mma_bf16(o_acc[2 * jj + 1], pal, vh[2], vh[3]);
                mma_bf16(o_acc[2 * jj + 1], pah, vl[2], vl[3]);
            }
        }
    }

    const float inv0 = 1.f / l_run[0];
    const float inv1 = 1.f / l_run[1];
    const int s0 = q0 + m0 + g;
    const int s1 = s0 + 8;
    __half* d0 = O + (((size_t)(b * S_LEN + s0)) * H_Q + h) * HDIM;
    __half* d1 = O + (((size_t)(b * S_LEN + s1)) * H_Q + h) * HDIM;
#pragma unroll
    for (int n = 0; n < 16; n++) {
        const int col = (n << 3) + (c << 1);
        *(__half2*)(d0 + col) = __floats2half2_rn(o_acc[n][0] * inv0, o_acc[n][1] * inv0);
        *(__half2*)(d1 + col) = __floats2half2_rn(o_acc[n][2] * inv1, o_acc[n][3] * inv1);
    }
}

// ---------------------------------------------------------------------------
extern "C" void kernel_launch(void* const* d_in, const int* in_sizes, int n_in,
                              void* d_out, int out_size)
{
    const float* x    = (const float*)d_in[0];
    const float* wq   = (const float*)d_in[1];
    const float* wk   = (const float*)d_in[2];
    const float* wv   = (const float*)d_in[3];
    const float* wo   = (const float*)d_in[4];
    const float* cosb = (const float*)d_in[5];
    const float* sinb = (const float*)d_in[6];
    float* out = (float*)d_out;

    float *Q, *K, *V;
    __half *x16, *wq16, *wk16, *wv16, *wo16, *Ah;
    cudaGetSymbolAddress((void**)&Q, g_Q);
    cudaGetSymbolAddress((void**)&K, g_K);
    cudaGetSymbolAddress((void**)&V, g_V);
    cudaGetSymbolAddress((void**)&x16, g_x16);
    cudaGetSymbolAddress((void**)&wq16, g_wq16);
    cudaGetSymbolAddress((void**)&wk16, g_wk16);
    cudaGetSymbolAddress((void**)&wv16, g_wv16);
    cudaGetSymbolAddress((void**)&wo16, g_wo16);
    cudaGetSymbolAddress((void**)&Ah, g_Ah);

    const int M = BATCH * S_LEN;   // 4096

    cudaFuncSetAttribute(hgemm, cudaFuncAttributeMaxDynamicSharedMemorySize, GEMM_SMEM);
    cudaFuncSetAttribute(flash_bf16, cudaFuncAttributeMaxDynamicSharedMemorySize, FLASH_SMEM);

    // Convert inputs/weights to fp16 once
    f2h<<<(4096 * 1024) / 256, 256>>>(x, x16, 4096 * 1024);
    f2h<<<(4096 * 1024) / 256, 256>>>(wq, wq16, 4096 * 1024);
    f2h<<<(1024 * 1024) / 256, 256>>>(wk, wk16, 1024 * 1024);
    f2h<<<(1024 * 1024) / 256, 256>>>(wv, wv16, 1024 * 1024);
    f2h<<<(4096 * 1024) / 256, 256>>>(wo, wo16, 4096 * 1024);

    // QKV projections (fp16 cp.async GEMM, head-permuted stores)
    hgemm<<<dim3((H_Q * HDIM) / 256, M / 128), 256, GEMM_SMEM>>>(x16, wq16, Q, 0, 1, H_Q);
    hgemm<<<dim3((H_KV * HDIM) / 256, M / 128), 256, GEMM_SMEM>>>(x16, wk16, K, 0, 1, H_KV);
    hgemm<<<dim3((H_KV * HDIM) / 256, M / 128), 256, GEMM_SMEM>>>(x16, wv16, V, 0, 1, H_KV);

    // RoPE on Q and K
    const int qpairs = BATCH * H_Q * S_LEN * (HDIM / 2);
    const int kpairs = BATCH * H_KV * S_LEN * (HDIM / 2);
    rope_kernel<<<(qpairs + 255) / 256, 256>>>(Q, cosb, sinb, qpairs);
    rope_kernel<<<(kpairs + 255) / 256, 256>>>(K, cosb, sinb, kpairs);

    // Flash attention (split-bf16 mma) -> fp16 A
    flash_bf16<<<dim3(S_LEN / 128, H_Q, BATCH), 256, FLASH_SMEM>>>(Q, K, V, Ah);

    // Output projection
    hgemm<<<dim3(D_DIM / 256, M / 128), 256, GEMM_SMEM>>>(Ah, wo16, out, D_DIM, 0, 0);
}

// round 11
// speedup vs baseline: 2.4174x; 1.0623x over previous
#include <cuda_runtime.h>
#include <cuda_bf16.h>
#include <cuda_fp16.h>
#include <cstdint>

#define S_LEN 2048
#define D_DIM 4096
#define H_Q   32
#define H_KV  8
#define HDIM  128
#define BATCH 2
#define K_DIM 4096

#define QTOT  (BATCH * H_Q * S_LEN * HDIM)
#define KVTOT (BATCH * H_KV * S_LEN * HDIM)

// Scratch (allocation-free rule: __device__ globals)
__device__ float g_Q[QTOT];                    // [B, H, S, HD] fp32 (pre-rope)
__device__ float g_K[KVTOT];
__device__ float g_V[KVTOT];
__device__ __half g_x16[4096 * 4096];
__device__ __half g_wq16[4096 * 4096];
__device__ __half g_wk16[1024 * 4096];
__device__ __half g_wv16[1024 * 4096];
__device__ __half g_wo16[4096 * 4096];
__device__ __half g_Ah[4096 * 4096];           // flash out, fp16
__device__ __nv_bfloat16 g_Qh[QTOT], g_Ql[QTOT];       // split Q (roped+scaled)
__device__ __nv_bfloat16 g_Kh[KVTOT], g_Kl[KVTOT];     // split K (roped)
__device__ __nv_bfloat16 g_Vh[KVTOT], g_Vl[KVTOT];     // split V

// ---------------------------------------------------------------------------
// fp32 -> fp16 convert (vectorized)
// ---------------------------------------------------------------------------
__global__ void f2h(const float* __restrict__ s, __half* __restrict__ d, int n4)
{
    const int i = blockIdx.x * blockDim.x + threadIdx.x;
    if (i >= n4) return;
    const float4 f = ((const float4*)s)[i];
    __half2 h0 = __floats2half2_rn(f.x, f.y);
    __half2 h1 = __floats2half2_rn(f.z, f.w);
    ((uint2*)d)[i] = make_uint2(*(uint32_t*)&h0, *(uint32_t*)&h1);
}

// ---------------------------------------------------------------------------
// FP16 NT GEMM, cp.async 3-stage pipeline (R10-proven, untouched)
// ---------------------------------------------------------------------------
#define STG_BYTES (384 * 144)
#define NSTG 3
#define GEMM_SMEM (NSTG * STG_BYTES)

__device__ __forceinline__ void cp16(uint32_t dst, const void* src) {
    asm volatile("cp.async.ca.shared.global [%0], [%1], 16;"
                 :: "r"(dst), "l"(src));
}
__device__ __forceinline__ void mma_h(float* d, const uint32_t* a,
                                      uint32_t b0, uint32_t b1) {
    asm volatile(
        "mma.sync.aligned.m16n8k16.row.col.f32.f16.f16.f32 "
        "{%0,%1,%2,%3}, {%4,%5,%6,%7}, {%8,%9}, {%0,%1,%2,%3};"
        : "+f"(d[0]), "+f"(d[1]), "+f"(d[2]), "+f"(d[3])
        : "r"(a[0]), "r"(a[1]), "r"(a[2]), "r"(a[3]), "r"(b0), "r"(b1));
}

__device__ __forceinline__ void hgemm_issue(
    uint32_t sdst, const __half* __restrict__ A, const __half* __restrict__ B,
    int bm, int bn, int k0, int tid)
{
#pragma unroll
    for (int i = 0; i < 4; i++) {
        const int q = tid + (i << 8);
        const int row = q >> 3, j = q & 7;
        cp16(sdst + row * 144 + (j << 4),
             A + (size_t)(bm + row) * K_DIM + k0 + (j << 3));
    }
#pragma unroll
    for (int i = 4; i < 12; i++) {
        const int q = tid + (i << 8);
        const int row = q >> 3, j = q & 7;
        cp16(sdst + row * 144 + (j << 4),
             B + (size_t)(bn + row - 128) * K_DIM + k0 + (j << 3));
    }
}

__global__ __launch_bounds__(256, 1)
void hgemm(const __half* __restrict__ A, const __half* __restrict__ B,
           float* __restrict__ C, int N, int mode, int HC)
{
    extern __shared__ char gsm[];
    const uint32_t sbase = (uint32_t)__cvta_generic_to_shared(gsm);
    const int tid = threadIdx.x;
    const int bm = blockIdx.y << 7;
    const int bn = blockIdx.x << 8;

    const int wid = tid >> 5, lane = tid & 31;
    const int wm = (wid >> 2) << 6;
    const int wn = (wid & 3) << 6;
    const int g = lane >> 2;
    const int c = lane & 3;

    float acc[4][8][4];
#pragma unroll
    for (int mt = 0; mt < 4; mt++)
#pragma unroll
        for (int nt = 0; nt < 8; nt++)
#pragma unroll
            for (int e = 0; e < 4; e++) acc[mt][nt][e] = 0.f;

    hgemm_issue(sbase, A, B, bm, bn, 0, tid);
    asm volatile("cp.async.commit_group;" ::: "memory");
    hgemm_issue(sbase + STG_BYTES, A, B, bm, bn, 64, tid);
    asm volatile("cp.async.commit_group;" ::: "memory");

    const int NST = K_DIM / 64;
    int buf = 0;
    for (int s = 0; s < NST; s++) {
        asm volatile("cp.async.wait_group 1;" ::: "memory");
        __syncthreads();

        const uint32_t* Sw = (const uint32_t*)(gsm + buf * STG_BYTES);
        const uint32_t* Bw = Sw + 128 * 36;
#pragma unroll
        for (int kq = 0; kq < 4; kq++) {
            const int kc = (kq << 3) + c;
            uint32_t af[4][4];
#pragma unroll
            for (int mt = 0; mt < 4; mt++) {
                const int m0 = wm + (mt << 4) + g;
                af[mt][0] = Sw[m0 * 36 + kc];
                af[mt][1] = Sw[(m0 + 8) * 36 + kc];
                af[mt][2] = Sw[m0 * 36 + kc + 4];
                af[mt][3] = Sw[(m0 + 8) * 36 + kc + 4];
            }
#pragma unroll
            for (int nt = 0; nt < 8; nt++) {
                const int n0 = wn + (nt << 3) + g;
                const uint32_t b0 = Bw[n0 * 36 + kc];
                const uint32_t b1 = Bw[n0 * 36 + kc + 4];
#pragma unroll
                for (int mt = 0; mt < 4; mt++)
                    mma_h(acc[mt][nt], af[mt], b0, b1);
            }
        }
        __syncthreads();

        if (s + 2 < NST) {
            const int nb = (buf + 2 >= NSTG) ? buf + 2 - NSTG : buf + 2;
            hgemm_issue(sbase + nb * STG_BYTES, A, B, bm, bn, (s + 2) << 6, tid);
            asm volatile("cp.async.commit_group;" ::: "memory");
        }
        buf = (buf + 1 == NSTG) ? 0 : buf + 1;
    }

#pragma unroll
    for (int mt = 0; mt < 4; mt++) {
#pragma unroll
        for (int nt = 0; nt < 8; nt++) {
            const int row = bm + wm + (mt << 4) + g;
            const int col = bn + wn + (nt << 3) + (c << 1);
            float2 lo = make_float2(acc[mt][nt][0], acc[mt][nt][1]);
            float2 hi = make_float2(acc[mt][nt][2], acc[mt][nt][3]);
            if (mode == 0) {
                *(float2*)&C[(size_t)row * N + col] = lo;
                *(float2*)&C[(size_t)(row + 8) * N + col] = hi;
            } else {
                const int hh = col >> 7, hd = col & (HDIM - 1);
                const int b0 = row >> 11, s0 = row & (S_LEN - 1);
                const int b1 = (row + 8) >> 11, s1 = (row + 8) & (S_LEN - 1);
                *(float2*)&C[(((size_t)(b0 * HC + hh)) * S_LEN + s0) * HDIM + hd] = lo;
                *(float2*)&C[(((size_t)(b1 * HC + hh)) * S_LEN + s1) * HDIM + hd] = hi;
            }
        }
    }
}

// ---------------------------------------------------------------------------
// Split helpers
// ---------------------------------------------------------------------------
__device__ __forceinline__ void bsplit(float x, __nv_bfloat16& h, __nv_bfloat16& l) {
    h = __float2bfloat16(x);
    l = __float2bfloat16(x - __bfloat162float(h));
}

// RoPE + scale(log2e) + bf16 hi/lo split for Q. i indexes (even,odd) pairs.
__global__ void rope_split_q(const float* __restrict__ Q,
                             __nv_bfloat16* __restrict__ Qh, __nv_bfloat16* __restrict__ Ql,
                             const float* __restrict__ cosb, const float* __restrict__ sinb,
                             int npairs)
{
    const int i = blockIdx.x * blockDim.x + threadIdx.x;
    if (i >= npairs) return;
    const float scale = 0.08838834764831845f * 1.44269504088896340f;  // 1/sqrt(128)*log2e
    const int p = i & 63;
    const int s = (i >> 6) & (S_LEN - 1);
    const float c = cosb[(s << 6) + p];
    const float sn = sinb[(s << 6) + p];
    const float2 v = ((const float2*)Q)[i];
    float2 o;
    o.x = (v.x * c - v.y * sn) * scale;
    o.y = (v.x * sn + v.y * c) * scale;
    __nv_bfloat16 h0, l0, h1, l1;
    bsplit(o.x, h0, l0); bsplit(o.y, h1, l1);
    ((__nv_bfloat162*)Qh)[i] = __nv_bfloat162(h0, h1);
    ((__nv_bfloat162*)Ql)[i] = __nv_bfloat162(l0, l1);
}

// RoPE + split for K (no scale)
__global__ void rope_split_k(const float* __restrict__ K,
                             __nv_bfloat16* __restrict__ Kh, __nv_bfloat16* __restrict__ Kl,
                             const float* __restrict__ cosb, const float* __restrict__ sinb,
                             int npairs)
{
    const int i = blockIdx.x * blockDim.x + threadIdx.x;
    if (i >= npairs) return;
    const int p = i & 63;
    const int s = (i >> 6) & (S_LEN - 1);
    const float c = cosb[(s << 6) + p];
    const float sn = sinb[(s << 6) + p];
    const float2 v = ((const float2*)K)[i];
    float2 o;
    o.x = v.x * c - v.y * sn;
    o.y = v.x * sn + v.y * c;
    __nv_bfloat16 h0, l0, h1, l1;
    bsplit(o.x, h0, l0); bsplit(o.y, h1, l1);
    ((__nv_bfloat162*)Kh)[i] = __nv_bfloat162(h0, h1);
    ((__nv_bfloat162*)Kl)[i] = __nv_bfloat162(l0, l1);
}

// Plain split for V
__global__ void vsplit(const float* __restrict__ V,
                       __nv_bfloat16* __restrict__ Vh, __nv_bfloat16* __restrict__ Vl,
                       int npairs)
{
    const int i = blockIdx.x * blockDim.x + threadIdx.x;
    if (i >= npairs) return;
    const float2 v = ((const float2*)V)[i];
    __nv_bfloat16 h0, l0, h1, l1;
    bsplit(v.x, h0, l0); bsplit(v.y, h1, l1);
    ((__nv_bfloat162*)Vh)[i] = __nv_bfloat162(h0, h1);
    ((__nv_bfloat162*)Vl)[i] = __nv_bfloat162(l0, l1);
}

// ---------------------------------------------------------------------------
// Flash attention: split-bf16 mma core (R10-proven), pre-split operands,
// cp.async 2-stage K/V pipeline, exp2 softmax (scale folded upstream).
// ---------------------------------------------------------------------------
#define FSTR 136
#define KVS_H (4 * 64 * FSTR)                    // halfs per KV stage
#define KVS_B (KVS_H * 2)                        // bytes  (69632)
#define FLASH_SMEM ((2 * 128 * FSTR) * 2 + 2 * KVS_B)   // 208896 B

__device__ __forceinline__ void ldsm4(uint32_t* r, const __nv_bfloat16* p) {
    uint32_t a = (uint32_t)__cvta_generic_to_shared(p);
    asm volatile("ldmatrix.sync.aligned.m8n8.x4.shared.b16 {%0,%1,%2,%3}, [%4];"
                 : "=r"(r[0]), "=r"(r[1]), "=r"(r[2]), "=r"(r[3]) : "r"(a));
}
__device__ __forceinline__ void ldsm4t(uint32_t* r, const __nv_bfloat16* p) {
    uint32_t a = (uint32_t)__cvta_generic_to_shared(p);
    asm volatile("ldmatrix.sync.aligned.m8n8.x4.trans.shared.b16 {%0,%1,%2,%3}, [%4];"
                 : "=r"(r[0]), "=r"(r[1]), "=r"(r[2]), "=r"(r[3]) : "r"(a));
}
__device__ __forceinline__ void mma_bf16(float* d, const uint32_t* a,
                                         uint32_t b0, uint32_t b1) {
    asm volatile(
        "mma.sync.aligned.m16n8k16.row.col.f32.bf16.bf16.f32 "
        "{%0,%1,%2,%3}, {%4,%5,%6,%7}, {%8,%9}, {%0,%1,%2,%3};"
        : "+f"(d[0]), "+f"(d[1]), "+f"(d[2]), "+f"(d[3])
        : "r"(a[0]), "r"(a[1]), "r"(a[2]), "r"(a[3]), "r"(b0), "r"(b1));
}
__device__ __forceinline__ uint32_t packbf(float a, float b) {
    __nv_bfloat162 t = __floats2bfloat162_rn(a, b);
    return *(uint32_t*)&t;
}

// Issue one K/V stage via cp.async. 16 chunks x 16B per thread = 64KB/CTA.
__device__ __forceinline__ void kv_issue(
    uint32_t skv, int bi,
    const __nv_bfloat16* __restrict__ Khg, const __nv_bfloat16* __restrict__ Klg,
    const __nv_bfloat16* __restrict__ Vhg, const __nv_bfloat16* __restrict__ Vlg,
    int j0, int tid)
{
    const int pr = tid >> 2;          // row 0..63
    const int jb = tid & 3;           // chunk group
    const uint32_t dst0 = skv + bi * KVS_B + pr * (FSTR * 2);
    const size_t src0 = (size_t)(j0 + pr) * HDIM;
    const __nv_bfloat16* arr[4] = {Khg, Klg, Vhg, Vlg};
#pragma unroll
    for (int a = 0; a < 4; a++) {
        const uint32_t d = dst0 + a * (64 * FSTR * 2);
        const __nv_bfloat16* s = arr[a] + src0;
#pragma unroll
        for (int i = 0; i < 4; i++) {
            const int j = jb + (i << 2);          // 16B chunk index 0..15
            cp16(d + (j << 4), s + (j << 3));
        }
    }
}

__global__ __launch_bounds__(256, 1)
void flash_bf16(const __nv_bfloat16* __restrict__ Qhg, const __nv_bfloat16* __restrict__ Qlg,
                const __nv_bfloat16* __restrict__ Khg, const __nv_bfloat16* __restrict__ Klg,
                const __nv_bfloat16* __restrict__ Vhg, const __nv_bfloat16* __restrict__ Vlg,
                __half* __restrict__ O)
{
    extern __shared__ __nv_bfloat16 fsm[];
    __nv_bfloat16* Qh = fsm;
    __nv_bfloat16* Ql = Qh + 128 * FSTR;
    __nv_bfloat16* KV = Ql + 128 * FSTR;
    const uint32_t skv = (uint32_t)__cvta_generic_to_shared(KV);

    const int tid = threadIdx.x;
    const int lane = tid & 31;
    const int w = tid >> 5;
    const int g = lane >> 2;
    const int c = lane & 3;
    const int m0 = w << 4;

    const int q0 = blockIdx.x << 7;
    const int h  = blockIdx.y;
    const int b  = blockIdx.z;
    const int kvh = h >> 2;

    const size_t qbase = (((size_t)(b * H_Q + h)) * S_LEN + q0) * HDIM;
    const size_t kvbase = ((size_t)(b * H_KV + kvh)) * S_LEN * HDIM;
    const __nv_bfloat16* Khb = Khg + kvbase;
    const __nv_bfloat16* Klb = Klg + kvbase;
    const __nv_bfloat16* Vhb = Vhg + kvbase;
    const __nv_bfloat16* Vlb = Vlg + kvbase;

    // Issue KV stage 0 first (hide behind Q load)
    kv_issue(skv, 0, Khb, Klb, Vhb, Vlb, 0, tid);
    asm volatile("cp.async.commit_group;" ::: "memory");

    // Q tiles: pre-split, straight uint4 copies
    for (int v = tid; v < 2048; v += 256) {
        const int r = v >> 4, j8 = (v & 15) << 3;
        *(uint4*)&Qh[r * FSTR + j8] = *(const uint4*)(Qhg + qbase + r * HDIM + j8);
        *(uint4*)&Ql[r * FSTR + j8] = *(const uint4*)(Qlg + qbase + r * HDIM + j8);
    }

    float m_run[2] = {-1e30f, -1e30f};
    float l_run[2] = {0.f, 0.f};
    float o_acc[16][4];
#pragma unroll
    for (int n = 0; n < 16; n++)
#pragma unroll
        for (int e = 0; e < 4; e++) o_acc[n][e] = 0.f;

    const int a_row = m0 + (lane & 15);
    const int a_cofs = (lane >> 4) << 3;
    const int b_rofs = (lane & 7) + ((lane >> 4) << 3);
    const int b_cofs = ((lane >> 3) & 1) << 3;
    const int v_rofs = (lane & 7) + (((lane >> 3) & 1) << 3);
    const int v_cofs = (lane >> 4) << 3;

    const int ntiles = (q0 >> 6) + 2;
    for (int t = 0; t < ntiles; t++) {
        const bool more = (t + 1 < ntiles);
        if (more) {
            kv_issue(skv, (t + 1) & 1, Khb, Klb, Vhb, Vlb, (t + 1) << 6, tid);
            asm volatile("cp.async.commit_group;" ::: "memory");
            asm volatile("cp.async.wait_group 1;" ::: "memory");
        } else {
            asm volatile("cp.async.wait_group 0;" ::: "memory");
        }
        __syncthreads();

        const __nv_bfloat16* Khp = KV + (size_t)(t & 1) * KVS_H;
        const __nv_bfloat16* Klp = Khp + 64 * FSTR;
        const __nv_bfloat16* Vhp = Khp + 2 * 64 * FSTR;
        const __nv_bfloat16* Vlp = Khp + 3 * 64 * FSTR;

        // ---- S = Q K^T (split-bf16) ----
        float s[8][4];
#pragma unroll
        for (int n = 0; n < 8; n++)
#pragma unroll
            for (int e = 0; e < 4; e++) s[n][e] = 0.f;

#pragma unroll
        for (int ks = 0; ks < 8; ks++) {
            uint32_t qh[4], ql[4];
            ldsm4(qh, &Qh[a_row * FSTR + (ks << 4) + a_cofs]);
            ldsm4(ql, &Ql[a_row * FSTR + (ks << 4) + a_cofs]);
#pragma unroll
            for (int jj = 0; jj < 4; jj++) {
                uint32_t kh[4], kl[4];
                const int br = (jj << 4) + b_rofs;
                const int bc = (ks << 4) + b_cofs;
                ldsm4(kh, &Khp[br * FSTR + bc]);
                ldsm4(kl, &Klp[br * FSTR + bc]);
                mma_bf16(s[2 * jj],     qh, kh[0], kh[1]);
                mma_bf16(s[2 * jj],     qh, kl[0], kl[1]);
                mma_bf16(s[2 * jj],     ql, kh[0], kh[1]);
                mma_bf16(s[2 * jj + 1], qh, kh[2], kh[3]);
                mma_bf16(s[2 * jj + 1], qh, kl[2], kl[3]);
                mma_bf16(s[2 * jj + 1], ql, kh[2], kh[3]);
            }
        }

        // ---- causal mask ----
        const int j0 = t << 6;
        if (t >= ntiles - 2) {
            const int r0 = q0 + m0 + g, r1 = r0 + 8;
#pragma unroll
            for (int n = 0; n < 8; n++) {
                const int col = j0 + (n << 3) + (c << 1);
                if (col > r0)     s[n][0] = -1e30f;
                if (col + 1 > r0) s[n][1] = -1e30f;
                if (col > r1)     s[n][2] = -1e30f;
                if (col + 1 > r1) s[n][3] = -1e30f;
            }
        }

        // ---- online softmax (base-2; scale*log2e folded into Q) ----
        float mx0 = -1e30f, mx1 = -1e30f;
#pragma unroll
        for (int n = 0; n < 8; n++) {
            mx0 = fmaxf(mx0, fmaxf(s[n][0], s[n][1]));
            mx1 = fmaxf(mx1, fmaxf(s[n][2], s[n][3]));
        }
        mx0 = fmaxf(mx0, __shfl_xor_sync(0xffffffffu, mx0, 1));
        mx0 = fmaxf(mx0, __shfl_xor_sync(0xffffffffu, mx0, 2));
        mx1 = fmaxf(mx1, __shfl_xor_sync(0xffffffffu, mx1, 1));
        mx1 = fmaxf(mx1, __shfl_xor_sync(0xffffffffu, mx1, 2));

        const float mn0 = fmaxf(m_run[0], mx0);
        const float mn1 = fmaxf(m_run[1], mx1);
        const float alpha0 = exp2f(m_run[0] - mn0);
        const float alpha1 = exp2f(m_run[1] - mn1);
        m_run[0] = mn0; m_run[1] = mn1;

        float sum0 = 0.f, sum1 = 0.f;
        uint32_t ph[16], pl[16];
#pragma unroll
        for (int n = 0; n < 8; n++) {
            float p0 = exp2f(s[n][0] - mn0);
            float p1 = exp2f(s[n][1] - mn0);
            float p2 = exp2f(s[n][2] - mn1);
            float p3 = exp2f(s[n][3] - mn1);
            sum0 += p0 + p1; sum1 += p2 + p3;
            __nv_bfloat16 h0, l0, h1, l1;
            bsplit(p0, h0, l0); bsplit(p1, h1, l1);
            ph[2 * n] = packbf(__bfloat162float(h0), __bfloat162float(h1));
            pl[2 * n] = packbf(__bfloat162float(l0), __bfloat162float(l1));
            bsplit(p2, h0, l0); bsplit(p3, h1, l1);
            ph[2 * n + 1] = packbf(__bfloat162float(h0), __bfloat162float(h1));
            pl[2 * n + 1] = packbf(__bfloat162float(l0), __bfloat162float(l1));
        }
        sum0 += __shfl_xor_sync(0xffffffffu, sum0, 1);
        sum0 += __shfl_xor_sync(0xffffffffu, sum0, 2);
        sum1 += __shfl_xor_sync(0xffffffffu, sum1, 1);
        sum1 += __shfl_xor_sync(0xffffffffu, sum1, 2);
        l_run[0] = l_run[0] * alpha0 + sum0;
        l_run[1] = l_run[1] * alpha1 + sum1;

#pragma unroll
        for (int n = 0; n < 16; n++) {
            o_acc[n][0] *= alpha0; o_acc[n][1] *= alpha0;
            o_acc[n][2] *= alpha1; o_acc[n][3] *= alpha1;
        }

        // ---- O += P V ----
#pragma unroll
        for (int kk = 0; kk < 4; kk++) {
            uint32_t pah[4] = {ph[4 * kk], ph[4 * kk + 1], ph[4 * kk + 2], ph[4 * kk + 3]};
            uint32_t pal[4] = {pl[4 * kk], pl[4 * kk + 1], pl[4 * kk + 2], pl[4 * kk + 3]};
#pragma unroll
            for (int jj = 0; jj < 8; jj++) {
                uint32_t vh[4], vl[4];
                const int vr = (kk << 4) + v_rofs;
                const int vc = (jj << 4) + v_cofs;
                ldsm4t(vh, &Vhp[vr * FSTR + vc]);
                ldsm4t(vl, &Vlp[vr * FSTR + vc]);
                mma_bf16(o_acc[2 * jj],     pah, vh[0], vh[1]);
                mma_bf16(o_acc[2 * jj],     pal, vh[0], vh[1]);
                mma_bf16(o_acc[2 * jj],     pah, vl[0], vl[1]);
                mma_bf16(o_acc[2 * jj + 1], pah, vh[2], vh[3]);
                mma_bf16(o_acc[2 * jj + 1], pal, vh[2], vh[3]);
                mma_bf16(o_acc[2 * jj + 1], pah, vl[2], vl[3]);
            }
        }
        __syncthreads();   // all reads of this buffer done before next overwrite
    }

    const float inv0 = 1.f / l_run[0];
    const float inv1 = 1.f / l_run[1];
    const int s0 = q0 + m0 + g;
    const int s1 = s0 + 8;
    __half* d0 = O + (((size_t)(b * S_LEN + s0)) * H_Q + h) * HDIM;
    __half* d1 = O + (((size_t)(b * S_LEN + s1)) * H_Q + h) * HDIM;
#pragma unroll
    for (int n = 0; n < 16; n++) {
        const int col = (n << 3) + (c << 1);
        *(__half2*)(d0 + col) = __floats2half2_rn(o_acc[n][0] * inv0, o_acc[n][1] * inv0);
        *(__half2*)(d1 + col) = __floats2half2_rn(o_acc[n][2] * inv1, o_acc[n][3] * inv1);
    }
}

// ---------------------------------------------------------------------------
extern "C" void kernel_launch(void* const* d_in, const int* in_sizes, int n_in,
                              void* d_out, int out_size)
{
    const float* x    = (const float*)d_in[0];
    const float* wq   = (const float*)d_in[1];
    const float* wk   = (const float*)d_in[2];
    const float* wv   = (const float*)d_in[3];
    const float* wo   = (const float*)d_in[4];
    const float* cosb = (const float*)d_in[5];
    const float* sinb = (const float*)d_in[6];
    float* out = (float*)d_out;

    float *Q, *K, *V;
    __half *x16, *wq16, *wk16, *wv16, *wo16, *Ah;
    __nv_bfloat16 *Qh, *Ql, *Kh, *Kl, *Vh, *Vl;
    cudaGetSymbolAddress((void**)&Q, g_Q);
    cudaGetSymbolAddress((void**)&K, g_K);
    cudaGetSymbolAddress((void**)&V, g_V);
    cudaGetSymbolAddress((void**)&x16, g_x16);
    cudaGetSymbolAddress((void**)&wq16, g_wq16);
    cudaGetSymbolAddress((void**)&wk16, g_wk16);
    cudaGetSymbolAddress((void**)&wv16, g_wv16);
    cudaGetSymbolAddress((void**)&wo16, g_wo16);
    cudaGetSymbolAddress((void**)&Ah, g_Ah);
    cudaGetSymbolAddress((void**)&Qh, g_Qh);
    cudaGetSymbolAddress((void**)&Ql, g_Ql);
    cudaGetSymbolAddress((void**)&Kh, g_Kh);
    cudaGetSymbolAddress((void**)&Kl, g_Kl);
    cudaGetSymbolAddress((void**)&Vh, g_Vh);
    cudaGetSymbolAddress((void**)&Vl, g_Vl);

    const int M = BATCH * S_LEN;   // 4096

    cudaFuncSetAttribute(hgemm, cudaFuncAttributeMaxDynamicSharedMemorySize, GEMM_SMEM);
    cudaFuncSetAttribute(flash_bf16, cudaFuncAttributeMaxDynamicSharedMemorySize, FLASH_SMEM);

    // Convert inputs/weights to fp16 once
    f2h<<<(4096 * 1024) / 256, 256>>>(x, x16, 4096 * 1024);
    f2h<<<(4096 * 1024) / 256, 256>>>(wq, wq16, 4096 * 1024);
    f2h<<<(1024 * 1024) / 256, 256>>>(wk, wk16, 1024 * 1024);
    f2h<<<(1024 * 1024) / 256, 256>>>(wv, wv16, 1024 * 1024);
    f2h<<<(4096 * 1024) / 256, 256>>>(wo, wo16, 4096 * 1024);

    // QKV projections (fp16 cp.async GEMM, head-permuted stores)
    hgemm<<<dim3((H_Q * HDIM) / 256, M / 128), 256, GEMM_SMEM>>>(x16, wq16, Q, 0, 1, H_Q);
    hgemm<<<dim3((H_KV * HDIM) / 256, M / 128), 256, GEMM_SMEM>>>(x16, wk16, K, 0, 1, H_KV);
    hgemm<<<dim3((H_KV * HDIM) / 256, M / 128), 256, GEMM_SMEM>>>(x16, wv16, V, 0, 1, H_KV);

    // RoPE + bf16 hi/lo pre-split (once, hoisted out of flash)
    const int qpairs = QTOT / 2;
    const int kvpairs = KVTOT / 2;
    rope_split_q<<<(qpairs + 255) / 256, 256>>>(Q, Qh, Ql, cosb, sinb, qpairs);
    rope_split_k<<<(kvpairs + 255) / 256, 256>>>(K, Kh, Kl, cosb, sinb, kvpairs);
    vsplit<<<(kvpairs + 255) / 256, 256>>>(V, Vh, Vl, kvpairs);

    // Flash attention (pre-split operands, cp.async pipeline) -> fp16 A
    flash_bf16<<<dim3(S_LEN / 128, H_Q, BATCH), 256, FLASH_SMEM>>>(
        Qh, Ql, Kh, Kl, Vh, Vl, Ah);

    // Output projection
    hgemm<<<dim3(D_DIM / 256, M / 128), 256, GEMM_SMEM>>>(Ah, wo16, out, D_DIM, 0, 0);
}

// round 12
// speedup vs baseline: 2.7320x; 1.1302x over previous
#include <cuda_runtime.h>
#include <cuda_bf16.h>
#include <cuda_fp16.h>
#include <cstdint>

#define S_LEN 2048
#define D_DIM 4096
#define H_Q   32
#define H_KV  8
#define HDIM  128
#define BATCH 2
#define K_DIM 4096

#define QTOT  (BATCH * H_Q * S_LEN * HDIM)
#define KVTOT (BATCH * H_KV * S_LEN * HDIM)

// Scratch (allocation-free rule: __device__ globals)
__device__ float g_Q[QTOT];                    // [B, H, S, HD] fp32 (pre-rope)
__device__ float g_K[KVTOT];
__device__ __half g_V16[KVTOT];                // V fp16 (straight from GEMM)
__device__ __half g_x16[4096 * 4096];
__device__ __half g_wq16[4096 * 4096];
__device__ __half g_wk16[1024 * 4096];
__device__ __half g_wv16[1024 * 4096];
__device__ __half g_wo16[4096 * 4096];
__device__ __half g_Ah[4096 * 4096];           // flash out, fp16
__device__ __nv_bfloat16 g_Qh[QTOT], g_Ql[QTOT];       // split Q (roped+scaled)
__device__ __nv_bfloat16 g_Kh[KVTOT], g_Kl[KVTOT];     // split K (roped)

// ---------------------------------------------------------------------------
// fp32 -> fp16 convert (vectorized)
// ---------------------------------------------------------------------------
__global__ void f2h(const float* __restrict__ s, __half* __restrict__ d, int n4)
{
    const int i = blockIdx.x * blockDim.x + threadIdx.x;
    if (i >= n4) return;
    const float4 f = ((const float4*)s)[i];
    __half2 h0 = __floats2half2_rn(f.x, f.y);
    __half2 h1 = __floats2half2_rn(f.z, f.w);
    ((uint2*)d)[i] = make_uint2(*(uint32_t*)&h0, *(uint32_t*)&h1);
}

// ---------------------------------------------------------------------------
// FP16 NT GEMM, cp.async 3-stage pipeline (R10-proven).
// mode 0: fp32 row-major. mode 1: fp32 head-permuted. mode 2: fp16 head-perm.
// ---------------------------------------------------------------------------
#define STG_BYTES (384 * 144)
#define NSTG 3
#define GEMM_SMEM (NSTG * STG_BYTES)

__device__ __forceinline__ void cp16(uint32_t dst, const void* src) {
    asm volatile("cp.async.ca.shared.global [%0], [%1], 16;"
                 :: "r"(dst), "l"(src));
}
__device__ __forceinline__ void mma_h(float* d, const uint32_t* a,
                                      uint32_t b0, uint32_t b1) {
    asm volatile(
        "mma.sync.aligned.m16n8k16.row.col.f32.f16.f16.f32 "
        "{%0,%1,%2,%3}, {%4,%5,%6,%7}, {%8,%9}, {%0,%1,%2,%3};"
        : "+f"(d[0]), "+f"(d[1]), "+f"(d[2]), "+f"(d[3])
        : "r"(a[0]), "r"(a[1]), "r"(a[2]), "r"(a[3]), "r"(b0), "r"(b1));
}

__device__ __forceinline__ void hgemm_issue(
    uint32_t sdst, const __half* __restrict__ A, const __half* __restrict__ B,
    int bm, int bn, int k0, int tid)
{
#pragma unroll
    for (int i = 0; i < 4; i++) {
        const int q = tid + (i << 8);
        const int row = q >> 3, j = q & 7;
        cp16(sdst + row * 144 + (j << 4),
             A + (size_t)(bm + row) * K_DIM + k0 + (j << 3));
    }
#pragma unroll
    for (int i = 4; i < 12; i++) {
        const int q = tid + (i << 8);
        const int row = q >> 3, j = q & 7;
        cp16(sdst + row * 144 + (j << 4),
             B + (size_t)(bn + row - 128) * K_DIM + k0 + (j << 3));
    }
}

__global__ __launch_bounds__(256, 1)
void hgemm(const __half* __restrict__ A, const __half* __restrict__ B,
           float* __restrict__ C, int N, int mode, int HC)
{
    extern __shared__ char gsm[];
    const uint32_t sbase = (uint32_t)__cvta_generic_to_shared(gsm);
    const int tid = threadIdx.x;
    const int bm = blockIdx.y << 7;
    const int bn = blockIdx.x << 8;

    const int wid = tid >> 5, lane = tid & 31;
    const int wm = (wid >> 2) << 6;
    const int wn = (wid & 3) << 6;
    const int g = lane >> 2;
    const int c = lane & 3;

    float acc[4][8][4];
#pragma unroll
    for (int mt = 0; mt < 4; mt++)
#pragma unroll
        for (int nt = 0; nt < 8; nt++)
#pragma unroll
            for (int e = 0; e < 4; e++) acc[mt][nt][e] = 0.f;

    hgemm_issue(sbase, A, B, bm, bn, 0, tid);
    asm volatile("cp.async.commit_group;" ::: "memory");
    hgemm_issue(sbase + STG_BYTES, A, B, bm, bn, 64, tid);
    asm volatile("cp.async.commit_group;" ::: "memory");

    const int NST = K_DIM / 64;
    int buf = 0;
    for (int s = 0; s < NST; s++) {
        asm volatile("cp.async.wait_group 1;" ::: "memory");
        __syncthreads();

        const uint32_t* Sw = (const uint32_t*)(gsm + buf * STG_BYTES);
        const uint32_t* Bw = Sw + 128 * 36;
#pragma unroll
        for (int kq = 0; kq < 4; kq++) {
            const int kc = (kq << 3) + c;
            uint32_t af[4][4];
#pragma unroll
            for (int mt = 0; mt < 4; mt++) {
                const int m0 = wm + (mt << 4) + g;
                af[mt][0] = Sw[m0 * 36 + kc];
                af[mt][1] = Sw[(m0 + 8) * 36 + kc];
                af[mt][2] = Sw[m0 * 36 + kc + 4];
                af[mt][3] = Sw[(m0 + 8) * 36 + kc + 4];
            }
#pragma unroll
            for (int nt = 0; nt < 8; nt++) {
                const int n0 = wn + (nt << 3) + g;
                const uint32_t b0 = Bw[n0 * 36 + kc];
                const uint32_t b1 = Bw[n0 * 36 + kc + 4];
#pragma unroll
                for (int mt = 0; mt < 4; mt++)
                    mma_h(acc[mt][nt], af[mt], b0, b1);
            }
        }
        __syncthreads();

        if (s + 2 < NST) {
            const int nb = (buf + 2 >= NSTG) ? buf + 2 - NSTG : buf + 2;
            hgemm_issue(sbase + nb * STG_BYTES, A, B, bm, bn, (s + 2) << 6, tid);
            asm volatile("cp.async.commit_group;" ::: "memory");
        }
        buf = (buf + 1 == NSTG) ? 0 : buf + 1;
    }

#pragma unroll
    for (int mt = 0; mt < 4; mt++) {
#pragma unroll
        for (int nt = 0; nt < 8; nt++) {
            const int row = bm + wm + (mt << 4) + g;
            const int col = bn + wn + (nt << 3) + (c << 1);
            float2 lo = make_float2(acc[mt][nt][0], acc[mt][nt][1]);
            float2 hi = make_float2(acc[mt][nt][2], acc[mt][nt][3]);
            if (mode == 0) {
                *(float2*)&C[(size_t)row * N + col] = lo;
                *(float2*)&C[(size_t)(row + 8) * N + col] = hi;
            } else {
                const int hh = col >> 7, hd = col & (HDIM - 1);
                const int b0 = row >> 11, s0 = row & (S_LEN - 1);
                const int b1 = (row + 8) >> 11, s1 = (row + 8) & (S_LEN - 1);
                const size_t i0 = (((size_t)(b0 * HC + hh)) * S_LEN + s0) * HDIM + hd;
                const size_t i1 = (((size_t)(b1 * HC + hh)) * S_LEN + s1) * HDIM + hd;
                if (mode == 1) {
                    *(float2*)&C[i0] = lo;
                    *(float2*)&C[i1] = hi;
                } else {
                    __half* Ch = (__half*)C;
                    *(__half2*)&Ch[i0] = __floats2half2_rn(lo.x, lo.y);
                    *(__half2*)&Ch[i1] = __floats2half2_rn(hi.x, hi.y);
                }
            }
        }
    }
}

// ---------------------------------------------------------------------------
// Split helpers
// ---------------------------------------------------------------------------
__device__ __forceinline__ void bsplit(float x, __nv_bfloat16& h, __nv_bfloat16& l) {
    h = __float2bfloat16(x);
    l = __float2bfloat16(x - __bfloat162float(h));
}

// RoPE + scale(log2e) + bf16 hi/lo split for Q
__global__ void rope_split_q(const float* __restrict__ Q,
                             __nv_bfloat16* __restrict__ Qh, __nv_bfloat16* __restrict__ Ql,
                             const float* __restrict__ cosb, const float* __restrict__ sinb,
                             int npairs)
{
    const int i = blockIdx.x * blockDim.x + threadIdx.x;
    if (i >= npairs) return;
    const float scale = 0.08838834764831845f * 1.44269504088896340f;
    const int p = i & 63;
    const int s = (i >> 6) & (S_LEN - 1);
    const float c = cosb[(s << 6) + p];
    const float sn = sinb[(s << 6) + p];
    const float2 v = ((const float2*)Q)[i];
    float2 o;
    o.x = (v.x * c - v.y * sn) * scale;
    o.y = (v.x * sn + v.y * c) * scale;
    __nv_bfloat16 h0, l0, h1, l1;
    bsplit(o.x, h0, l0); bsplit(o.y, h1, l1);
    ((__nv_bfloat162*)Qh)[i] = __nv_bfloat162(h0, h1);
    ((__nv_bfloat162*)Ql)[i] = __nv_bfloat162(l0, l1);
}

// RoPE + split for K (no scale)
__global__ void rope_split_k(const float* __restrict__ K,
                             __nv_bfloat16* __restrict__ Kh, __nv_bfloat16* __restrict__ Kl,
                             const float* __restrict__ cosb, const float* __restrict__ sinb,
                             int npairs)
{
    const int i = blockIdx.x * blockDim.x + threadIdx.x;
    if (i >= npairs) return;
    const int p = i & 63;
    const int s = (i >> 6) & (S_LEN - 1);
    const float c = cosb[(s << 6) + p];
    const float sn = sinb[(s << 6) + p];
    const float2 v = ((const float2*)K)[i];
    float2 o;
    o.x = v.x * c - v.y * sn;
    o.y = v.x * sn + v.y * c;
    __nv_bfloat16 h0, l0, h1, l1;
    bsplit(o.x, h0, l0); bsplit(o.y, h1, l1);
    ((__nv_bfloat162*)Kh)[i] = __nv_bfloat162(h0, h1);
    ((__nv_bfloat162*)Kl)[i] = __nv_bfloat162(l0, l1);
}

// ---------------------------------------------------------------------------
// Flash attention: split-bf16 QK^T + single-fp16 PV, cp.async 2-stage K/V,
// exp2 softmax, longest-first scheduling.
// ---------------------------------------------------------------------------
#define FSTR 136
#define KVS_H (3 * 64 * FSTR)                    // 16-bit elems per stage (Kh,Kl,V)
#define KVS_B (KVS_H * 2)                        // 52224 bytes
#define FLASH_SMEM ((2 * 128 * FSTR) * 2 + 2 * KVS_B)   // 174080 B

__device__ __forceinline__ void ldsm4(uint32_t* r, const void* p) {
    uint32_t a = (uint32_t)__cvta_generic_to_shared(p);
    asm volatile("ldmatrix.sync.aligned.m8n8.x4.shared.b16 {%0,%1,%2,%3}, [%4];"
                 : "=r"(r[0]), "=r"(r[1]), "=r"(r[2]), "=r"(r[3]) : "r"(a));
}
__device__ __forceinline__ void ldsm4t(uint32_t* r, const void* p) {
    uint32_t a = (uint32_t)__cvta_generic_to_shared(p);
    asm volatile("ldmatrix.sync.aligned.m8n8.x4.trans.shared.b16 {%0,%1,%2,%3}, [%4];"
                 : "=r"(r[0]), "=r"(r[1]), "=r"(r[2]), "=r"(r[3]) : "r"(a));
}
__device__ __forceinline__ void mma_bf16(float* d, const uint32_t* a,
                                         uint32_t b0, uint32_t b1) {
    asm volatile(
        "mma.sync.aligned.m16n8k16.row.col.f32.bf16.bf16.f32 "
        "{%0,%1,%2,%3}, {%4,%5,%6,%7}, {%8,%9}, {%0,%1,%2,%3};"
        : "+f"(d[0]), "+f"(d[1]), "+f"(d[2]), "+f"(d[3])
        : "r"(a[0]), "r"(a[1]), "r"(a[2]), "r"(a[3]), "r"(b0), "r"(b1));
}
__device__ __forceinline__ uint32_t packh2(float a, float b) {
    __half2 t = __floats2half2_rn(a, b);
    return *(uint32_t*)&t;
}

// Issue one K/V stage (Kh, Kl bf16 + V fp16) via cp.async. 48KB/CTA/stage.
__device__ __forceinline__ void kv_issue(
    uint32_t skv, int bi,
    const __nv_bfloat16* __restrict__ Khg, const __nv_bfloat16* __restrict__ Klg,
    const __half* __restrict__ Vg, int j0, int tid)
{
    const int pr = tid >> 2;          // row 0..63
    const int jb = tid & 3;
    const uint32_t dst0 = skv + bi * KVS_B + pr * (FSTR * 2);
    const size_t src0 = (size_t)(j0 + pr) * HDIM;
#pragma unroll
    for (int i = 0; i < 4; i++) {
        const int j = jb + (i << 2);
        cp16(dst0 + (j << 4), Khg + src0 + (j << 3));
        cp16(dst0 + (64 * FSTR * 2) + (j << 4), Klg + src0 + (j << 3));
        cp16(dst0 + (128 * FSTR * 2) + (j << 4), Vg + src0 + (j << 3));
    }
}

__global__ __launch_bounds__(256, 1)
void flash_bf16(const __nv_bfloat16* __restrict__ Qhg, const __nv_bfloat16* __restrict__ Qlg,
                const __nv_bfloat16* __restrict__ Khg, const __nv_bfloat16* __restrict__ Klg,
                const __half* __restrict__ Vg, __half* __restrict__ O)
{
    extern __shared__ __nv_bfloat16 fsm[];
    __nv_bfloat16* Qh = fsm;
    __nv_bfloat16* Ql = Qh + 128 * FSTR;
    __nv_bfloat16* KV = Ql + 128 * FSTR;
    const uint32_t skv = (uint32_t)__cvta_generic_to_shared(KV);

    const int tid = threadIdx.x;
    const int lane = tid & 31;
    const int w = tid >> 5;
    const int g = lane >> 2;
    const int c = lane & 3;
    const int m0 = w << 4;

    // Longest-first: blockIdx.x = 0 handles the LAST (longest) q-tile.
    const int q0 = (int)(gridDim.x - 1 - blockIdx.x) << 7;
    const int h  = blockIdx.y;
    const int b  = blockIdx.z;
    const int kvh = h >> 2;

    const size_t qbase = (((size_t)(b * H_Q + h)) * S_LEN + q0) * HDIM;
    const size_t kvbase = ((size_t)(b * H_KV + kvh)) * S_LEN * HDIM;
    const __nv_bfloat16* Khb = Khg + kvbase;
    const __nv_bfloat16* Klb = Klg + kvbase;
    const __half* Vb = Vg + kvbase;

    kv_issue(skv, 0, Khb, Klb, Vb, 0, tid);
    asm volatile("cp.async.commit_group;" ::: "memory");

    for (int v = tid; v < 2048; v += 256) {
        const int r = v >> 4, j8 = (v & 15) << 3;
        *(uint4*)&Qh[r * FSTR + j8] = *(const uint4*)(Qhg + qbase + r * HDIM + j8);
        *(uint4*)&Ql[r * FSTR + j8] = *(const uint4*)(Qlg + qbase + r * HDIM + j8);
    }

    float m_run[2] = {-1e30f, -1e30f};
    float l_run[2] = {0.f, 0.f};
    float o_acc[16][4];
#pragma unroll
    for (int n = 0; n < 16; n++)
#pragma unroll
        for (int e = 0; e < 4; e++) o_acc[n][e] = 0.f;

    const int a_row = m0 + (lane & 15);
    const int a_cofs = (lane >> 4) << 3;
    const int b_rofs = (lane & 7) + ((lane >> 4) << 3);
    const int b_cofs = ((lane >> 3) & 1) << 3;
    const int v_rofs = (lane & 7) + (((lane >> 3) & 1) << 3);
    const int v_cofs = (lane >> 4) << 3;

    const int ntiles = (q0 >> 6) + 2;
    for (int t = 0; t < ntiles; t++) {
        const bool more = (t + 1 < ntiles);
        if (more) {
            kv_issue(skv, (t + 1) & 1, Khb, Klb, Vb, (t + 1) << 6, tid);
            asm volatile("cp.async.commit_group;" ::: "memory");
            asm volatile("cp.async.wait_group 1;" ::: "memory");
        } else {
            asm volatile("cp.async.wait_group 0;" ::: "memory");
        }
        __syncthreads();

        const __nv_bfloat16* Khp = KV + (size_t)(t & 1) * KVS_H;
        const __nv_bfloat16* Klp = Khp + 64 * FSTR;
        const __half* Vp = (const __half*)(Khp + 2 * 64 * FSTR);

        // ---- S = Q K^T (split-bf16) ----
        float s[8][4];
#pragma unroll
        for (int n = 0; n < 8; n++)
#pragma unroll
            for (int e = 0; e < 4; e++) s[n][e] = 0.f;

#pragma unroll
        for (int ks = 0; ks < 8; ks++) {
            uint32_t qh[4], ql[4];
            ldsm4(qh, &Qh[a_row * FSTR + (ks << 4) + a_cofs]);
            ldsm4(ql, &Ql[a_row * FSTR + (ks << 4) + a_cofs]);
#pragma unroll
            for (int jj = 0; jj < 4; jj++) {
                uint32_t kh[4], kl[4];
                const int br = (jj << 4) + b_rofs;
                const int bc = (ks << 4) + b_cofs;
                ldsm4(kh, &Khp[br * FSTR + bc]);
                ldsm4(kl, &Klp[br * FSTR + bc]);
                mma_bf16(s[2 * jj],     qh, kh[0], kh[1]);
                mma_bf16(s[2 * jj],     qh, kl[0], kl[1]);
                mma_bf16(s[2 * jj],     ql, kh[0], kh[1]);
                mma_bf16(s[2 * jj + 1], qh, kh[2], kh[3]);
                mma_bf16(s[2 * jj + 1], qh, kl[2], kl[3]);
                mma_bf16(s[2 * jj + 1], ql, kh[2], kh[3]);
            }
        }

        // ---- causal mask ----
        const int j0 = t << 6;
        if (t >= ntiles - 2) {
            const int r0 = q0 + m0 + g, r1 = r0 + 8;
#pragma unroll
            for (int n = 0; n < 8; n++) {
                const int col = j0 + (n << 3) + (c << 1);
                if (col > r0)     s[n][0] = -1e30f;
                if (col + 1 > r0) s[n][1] = -1e30f;
                if (col > r1)     s[n][2] = -1e30f;
                if (col + 1 > r1) s[n][3] = -1e30f;
            }
        }

        // ---- online softmax (base-2) ----
        float mx0 = -1e30f, mx1 = -1e30f;
#pragma unroll
        for (int n = 0; n < 8; n++) {
            mx0 = fmaxf(mx0, fmaxf(s[n][0], s[n][1]));
            mx1 = fmaxf(mx1, fmaxf(s[n][2], s[n][3]));
        }
        mx0 = fmaxf(mx0, __shfl_xor_sync(0xffffffffu, mx0, 1));
        mx0 = fmaxf(mx0, __shfl_xor_sync(0xffffffffu, mx0, 2));
        mx1 = fmaxf(mx1, __shfl_xor_sync(0xffffffffu, mx1, 1));
        mx1 = fmaxf(mx1, __shfl_xor_sync(0xffffffffu, mx1, 2));

        const float mn0 = fmaxf(m_run[0], mx0);
        const float mn1 = fmaxf(m_run[1], mx1);
        const float alpha0 = exp2f(m_run[0] - mn0);
        const float alpha1 = exp2f(m_run[1] - mn1);
        m_run[0] = mn0; m_run[1] = mn1;

        float sum0 = 0.f, sum1 = 0.f;
        uint32_t ph[16];   // fp16 P fragments
#pragma unroll
        for (int n = 0; n < 8; n++) {
            float p0 = exp2f(s[n][0] - mn0);
            float p1 = exp2f(s[n][1] - mn0);
            float p2 = exp2f(s[n][2] - mn1);
            float p3 = exp2f(s[n][3] - mn1);
            sum0 += p0 + p1; sum1 += p2 + p3;
            ph[2 * n]     = packh2(p0, p1);
            ph[2 * n + 1] = packh2(p2, p3);
        }
        sum0 += __shfl_xor_sync(0xffffffffu, sum0, 1);
        sum0 += __shfl_xor_sync(0xffffffffu, sum0, 2);
        sum1 += __shfl_xor_sync(0xffffffffu, sum1, 1);
        sum1 += __shfl_xor_sync(0xffffffffu, sum1, 2);
        l_run[0] = l_run[0] * alpha0 + sum0;
        l_run[1] = l_run[1] * alpha1 + sum1;

#pragma unroll
        for (int n = 0; n < 16; n++) {
            o_acc[n][0] *= alpha0; o_acc[n][1] *= alpha0;
            o_acc[n][2] *= alpha1; o_acc[n][3] *= alpha1;
        }

        // ---- O += P V (single fp16) ----
#pragma unroll
        for (int kk = 0; kk < 4; kk++) {
            uint32_t pa[4] = {ph[4 * kk], ph[4 * kk + 1], ph[4 * kk + 2], ph[4 * kk + 3]};
#pragma unroll
            for (int jj = 0; jj < 8; jj++) {
                uint32_t vv[4];
                ldsm4t(vv, &Vp[((kk << 4) + v_rofs) * FSTR + (jj << 4) + v_cofs]);
                mma_h(o_acc[2 * jj],     pa, vv[0], vv[1]);
                mma_h(o_acc[2 * jj + 1], pa, vv[2], vv[3]);
            }
        }
        __syncthreads();
    }

    const float inv0 = 1.f / l_run[0];
    const float inv1 = 1.f / l_run[1];
    const int s0 = q0 + m0 + g;
    const int s1 = s0 + 8;
    __half* d0 = O + (((size_t)(b * S_LEN + s0)) * H_Q + h) * HDIM;
    __half* d1 = O + (((size_t)(b * S_LEN + s1)) * H_Q + h) * HDIM;
#pragma unroll
    for (int n = 0; n < 16; n++) {
        const int col = (n << 3) + (c << 1);
        *(__half2*)(d0 + col) = __floats2half2_rn(o_acc[n][0] * inv0, o_acc[n][1] * inv0);
        *(__half2*)(d1 + col) = __floats2half2_rn(o_acc[n][2] * inv1, o_acc[n][3] * inv1);
    }
}

// ---------------------------------------------------------------------------
extern "C" void kernel_launch(void* const* d_in, const int* in_sizes, int n_in,
                              void* d_out, int out_size)
{
    const float* x    = (const float*)d_in[0];
    const float* wq   = (const float*)d_in[1];
    const float* wk   = (const float*)d_in[2];
    const float* wv   = (const float*)d_in[3];
    const float* wo   = (const float*)d_in[4];
    const float* cosb = (const float*)d_in[5];
    const float* sinb = (const float*)d_in[6];
    float* out = (float*)d_out;

    float *Q, *K;
    __half *V16, *x16, *wq16, *wk16, *wv16, *wo16, *Ah;
    __nv_bfloat16 *Qh, *Ql, *Kh, *Kl;
    cudaGetSymbolAddress((void**)&Q, g_Q);
    cudaGetSymbolAddress((void**)&K, g_K);
    cudaGetSymbolAddress((void**)&V16, g_V16);
    cudaGetSymbolAddress((void**)&x16, g_x16);
    cudaGetSymbolAddress((void**)&wq16, g_wq16);
    cudaGetSymbolAddress((void**)&wk16, g_wk16);
    cudaGetSymbolAddress((void**)&wv16, g_wv16);
    cudaGetSymbolAddress((void**)&wo16, g_wo16);
    cudaGetSymbolAddress((void**)&Ah, g_Ah);
    cudaGetSymbolAddress((void**)&Qh, g_Qh);
    cudaGetSymbolAddress((void**)&Ql, g_Ql);
    cudaGetSymbolAddress((void**)&Kh, g_Kh);
    cudaGetSymbolAddress((void**)&Kl, g_Kl);

    const int M = BATCH * S_LEN;   // 4096

    cudaFuncSetAttribute(hgemm, cudaFuncAttributeMaxDynamicSharedMemorySize, GEMM_SMEM);
    cudaFuncSetAttribute(flash_bf16, cudaFuncAttributeMaxDynamicSharedMemorySize, FLASH_SMEM);

    // Convert inputs/weights to fp16 once
    f2h<<<(4096 * 1024) / 256, 256>>>(x, x16, 4096 * 1024);
    f2h<<<(4096 * 1024) / 256, 256>>>(wq, wq16, 4096 * 1024);
    f2h<<<(1024 * 1024) / 256, 256>>>(wk, wk16, 1024 * 1024);
    f2h<<<(1024 * 1024) / 256, 256>>>(wv, wv16, 1024 * 1024);
    f2h<<<(4096 * 1024) / 256, 256>>>(wo, wo16, 4096 * 1024);

    // QKV projections; V goes straight to fp16 (mode 2)
    hgemm<<<dim3((H_Q * HDIM) / 256, M / 128), 256, GEMM_SMEM>>>(x16, wq16, Q, 0, 1, H_Q);
    hgemm<<<dim3((H_KV * HDIM) / 256, M / 128), 256, GEMM_SMEM>>>(x16, wk16, K, 0, 1, H_KV);
    hgemm<<<dim3((H_KV * HDIM) / 256, M / 128), 256, GEMM_SMEM>>>(x16, wv16, (float*)V16, 0, 2, H_KV);

    // RoPE + bf16 hi/lo pre-split
    const int qpairs = QTOT / 2;
    const int kvpairs = KVTOT / 2;
    rope_split_q<<<(qpairs + 255) / 256, 256>>>(Q, Qh, Ql, cosb, sinb, qpairs);
    rope_split_k<<<(kvpairs + 255) / 256, 256>>>(K, Kh, Kl, cosb, sinb, kvpairs);

    // Flash attention -> fp16 A
    flash_bf16<<<dim3(S_LEN / 128, H_Q, BATCH), 256, FLASH_SMEM>>>(
        Qh, Ql, Kh, Kl, V16, Ah);

    // Output projection
    hgemm<<<dim3(D_DIM / 256, M / 128), 256, GEMM_SMEM>>>(Ah, wo16, out, D_DIM, 0, 0);
}